// round 5
// baseline (speedup 1.0000x reference)
#include <cuda_runtime.h>
#include <stdint.h>

#define BB 8
#define NN 2048
#define CC 80
#define ROWF 84          // floats per box row: 4 box + 80 scores
#define NW 64            // uint32 words per mask row (2048/32)
#define OUT_K 200
#define SCORE_THR 0.01f
#define FULLM 0xFFFFFFFFu

// Persistent scratch (no allocations allowed)
__device__ uint32_t           g_mask[BB][NN][NW];          // 4 MB  : IoU>0.5 bitmask
__device__ unsigned long long g_ckey[BB][CC][OUT_K];       // (score_bits<<32)|~flatidx
__device__ int                g_cbox[BB][CC][OUT_K];       // original box index
__device__ int                g_ccnt[BB][CC];

// ---------------------------------------------------------------------------
// Kernel 1: IoU>0.5 bitmask. grid(NN/16, B), 256 threads.
//   thread = (4-row group, 32-col word). Division replaced by exact 2*inter>uni
//   compare with guarded __fdiv_rn fallback near the boundary (bit-exact).
// ---------------------------------------------------------------------------
__global__ __launch_bounds__(256) void iou_mask_kernel(const float* __restrict__ x) {
    const int b = blockIdx.y;
    const int r = threadIdx.x >> 6;        // 0..3
    const int w = threadIdx.x & 63;        // 0..63
    const int i0 = blockIdx.x * 16 + r * 4;

    __shared__ float4 sb[NN];              // 32 KB (xor-swizzled)
    __shared__ float  sa[NN];              // 8 KB

    const float* xb = x + (size_t)b * NN * ROWF;
    for (int j = threadIdx.x; j < NN; j += 256) {
        float4 v = *reinterpret_cast<const float4*>(xb + (size_t)j * ROWF);
        int pj = j ^ ((j >> 5) & 31);
        sb[pj] = v;
        sa[pj] = __fmul_rn(v.z - v.x, v.w - v.y);
    }
    __syncthreads();

    float4 bi[4]; float ai[4];
#pragma unroll
    for (int q = 0; q < 4; q++) {
        int pi = (i0 + q) ^ (((i0 + q) >> 5) & 31);
        bi[q] = sb[pi];
        ai[q] = sa[pi];
    }

    uint32_t word[4] = {0, 0, 0, 0};
    const int j0 = w * 32;
    const int m  = w & 31;
#pragma unroll 8
    for (int t = 0; t < 32; t++) {
        int pj = j0 + (t ^ m);             // swizzled: conflict-free
        float4 bj = sb[pj];
        float  aj = sa[pj];
#pragma unroll
        for (int q = 0; q < 4; q++) {
            float lx = fmaxf(bi[q].x, bj.x), ly = fmaxf(bi[q].y, bj.y);
            float rx = fminf(bi[q].z, bj.z), ry = fminf(bi[q].w, bj.w);
            float ww = fmaxf(__fadd_rn(rx, -lx), 0.f);
            float hh = fmaxf(__fadd_rn(ry, -ly), 0.f);
            float inter = __fmul_rn(ww, hh);
            float uni   = __fadd_rn(__fadd_rn(ai[q], aj), -inter);
            float lhs   = __fadd_rn(inter, inter);          // exact
            bool bit = lhs > uni;                            // == (inter/uni > 0.5) in reals
            if (fabsf(__fadd_rn(lhs, -uni)) <= __fmul_rn(1e-6f, uni)) {
                // ambiguous zone (real quotient within ~1e-6 of 0.5): exact path
                bit = __fdiv_rn(inter, fmaxf(uni, 1e-8f)) > 0.5f;
            }
            if (bit) word[q] |= 1u << t;
        }
    }
#pragma unroll
    for (int q = 0; q < 4; q++) g_mask[b][i0 + q][w] = word[q];
}

// ---------------------------------------------------------------------------
// Kernel 2: one block (256 thr) per (class, batch).
//   Register-resident bitonic sort of 2048 64-bit keys (8/thread):
//     j<8  : in-register,  8<=j<=128 : warp shfl,  j>=256 : smem (6 passes).
//   Then warp 0 runs bitmask NMS with alive mask in registers.
// ---------------------------------------------------------------------------
#define CSWAP(a, c, d) { if ((d) ? (v[a] < v[c]) : (v[a] > v[c])) \
                         { unsigned long long _t = v[a]; v[a] = v[c]; v[c] = _t; } }

__device__ __forceinline__ int ss(int i) { return i + (i >> 3); }  // stride-9 pad

__device__ __forceinline__ void shfl_pass(unsigned long long v[8], int jd, bool desc, int lane) {
    const bool takemax = (desc == ((lane & jd) == 0));
#pragma unroll
    for (int t = 0; t < 8; t++) {
        unsigned long long o = __shfl_xor_sync(FULLM, v[t], jd);
        if ((v[t] < o) == takemax) v[t] = o;
    }
}

__device__ __forceinline__ void smem_pass(unsigned long long* sk, unsigned long long v[8],
                                          int j, bool desc, int g0) {
    __syncthreads();
#pragma unroll
    for (int t = 0; t < 8; t++) sk[ss(g0 + t)] = v[t];
    __syncthreads();
    const bool takemax = (desc == ((g0 & j) == 0));
#pragma unroll
    for (int t = 0; t < 8; t++) {
        unsigned long long o = sk[ss((g0 + t) ^ j)];
        if ((v[t] < o) == takemax) v[t] = o;
    }
}

__device__ __forceinline__ void reg_merge(unsigned long long v[8], bool d) {
    CSWAP(0,4,d) CSWAP(1,5,d) CSWAP(2,6,d) CSWAP(3,7,d)
    CSWAP(0,2,d) CSWAP(1,3,d) CSWAP(4,6,d) CSWAP(5,7,d)
    CSWAP(0,1,d) CSWAP(2,3,d) CSWAP(4,5,d) CSWAP(6,7,d)
}

__global__ __launch_bounds__(256) void nms_kernel(const float* __restrict__ x) {
    const int b = blockIdx.y, c = blockIdx.x;
    __shared__ unsigned long long sk[NN + NN / 8];          // 18 KB padded

    const int tid  = threadIdx.x;
    const int lane = tid & 31;
    const int g0   = tid * 8;
    const float* xb = x + (size_t)b * NN * ROWF;

    unsigned long long v[8];
#pragma unroll
    for (int t = 0; t < 8; t++) {
        int i = g0 + t;
        uint32_t sbits = __float_as_uint(xb[(size_t)i * ROWF + 4 + c]);  // scores >= 0
        v[t] = ((unsigned long long)sbits << 32)
             | (unsigned long long)(FULLM - (uint32_t)i);   // idx tie-break
    }

    // k = 2, 4, 8 : fully in-register
    CSWAP(0,1,true) CSWAP(2,3,false) CSWAP(4,5,true) CSWAP(6,7,false)
    CSWAP(0,2,true) CSWAP(1,3,true)  CSWAP(4,6,false) CSWAP(5,7,false)
    CSWAP(0,1,true) CSWAP(2,3,true)  CSWAP(4,5,false) CSWAP(6,7,false)
    {
        const bool d8 = ((g0 & 8) == 0);
        reg_merge(v, d8);
    }

    // k = 16 .. 2048
#pragma unroll
    for (int k = 16; k <= NN; k <<= 1) {
        const bool desc = ((g0 & k) == 0);
#pragma unroll
        for (int j = k >> 1; j >= 256; j >>= 1) smem_pass(sk, v, j, desc, g0);
        const int jstart = (k >> 1 < 128) ? (k >> 1) : 128;
#pragma unroll
        for (int j = jstart; j >= 8; j >>= 1) shfl_pass(v, j >> 3, desc, lane);
        reg_merge(v, desc);
    }

    __syncthreads();
#pragma unroll
    for (int t = 0; t < 8; t++) sk[ss(g0 + t)] = v[t];
    __syncthreads();

    if (tid >= 32) return;                  // warp 0 finishes alone

    // alive bitmask over ORIGINAL indices: lane owns words 2*lane, 2*lane+1
    uint32_t a0 = FULLM, a1 = FULLM;
    int kept = 0;
    int p = 0;
    const uint32_t* mb = &g_mask[b][0][0];

    while (p < NN && kept < OUT_K) {
        int pp = p + lane;
        unsigned long long key = (pp < NN) ? sk[ss(pp)] : 0ull;
        float s = __uint_as_float((uint32_t)(key >> 32));
        bool sok = (pp < NN) && (s > SCORE_THR);
        int oi  = (int)(FULLM - (uint32_t)(key & FULLM));
        int wrd = (oi >> 5) & 63;
        uint32_t v0 = __shfl_sync(FULLM, a0, wrd >> 1);
        uint32_t v1 = __shfl_sync(FULLM, a1, wrd >> 1);
        uint32_t av = (wrd & 1) ? v1 : v0;
        bool alive = (av >> (oi & 31)) & 1u;

        uint32_t bal_s = __ballot_sync(FULLM, sok);
        uint32_t cand  = __ballot_sync(FULLM, sok && alive);
        if (cand == 0) {
            if (bal_s != FULLM) break;      // sorted: everything later fails score too
            p += 32;
            continue;
        }
        int l  = __ffs(cand) - 1;
        int pf = p + l;
        int oif = __shfl_sync(FULLM, oi, l);
        unsigned long long keyf = __shfl_sync(FULLM, key, l);
        if (lane == 0) {
            uint32_t sbits = (uint32_t)(keyf >> 32);
            uint32_t flat  = (uint32_t)(c * NN + pf);
            g_ckey[b][c][kept] = ((unsigned long long)sbits << 32)
                               | (unsigned long long)(FULLM - flat);
            g_cbox[b][c][kept] = oif;
        }
        kept++;
        const uint32_t* __restrict__ row = mb + (size_t)oif * NW;
        a0 &= ~row[2 * lane];
        a1 &= ~row[2 * lane + 1];           // self-bit in row clears oif from alive
        p = pf + 1;
    }
    if (lane == 0) g_ccnt[b][c] = kept;
}

// ---------------------------------------------------------------------------
// Kernel 3: per-batch top-200 merge of 80 sorted lists. grid(B), 32 threads.
//   Register-resident tournament: lane owns up to 3 class lists.
// ---------------------------------------------------------------------------
__global__ void topk_kernel(const float* __restrict__ x, float* __restrict__ out) {
    const int b = blockIdx.x;
    const int lane = threadIdx.x;

    int cnt[3]; int ptr[3]; unsigned long long cur[3];
#pragma unroll
    for (int s = 0; s < 3; s++) {
        int c = lane + 32 * s;
        if (c < CC) {
            cnt[s] = g_ccnt[b][c];
            ptr[s] = 0;
            cur[s] = (cnt[s] > 0) ? g_ckey[b][c][0] : 0ull;
        } else { cnt[s] = 0; ptr[s] = 0; cur[s] = 0ull; }
    }

    for (int k = 0; k < OUT_K; k++) {
        unsigned long long m = cur[0];
        if (cur[1] > m) m = cur[1];
        if (cur[2] > m) m = cur[2];
        unsigned long long g = m;
#pragma unroll
        for (int off = 16; off > 0; off >>= 1) {
            unsigned long long o = __shfl_xor_sync(FULLM, g, off);
            if (o > g) g = o;
        }
        uint32_t win = __ballot_sync(FULLM, (m == g) && (g != 0ull));
        float* o = out + ((size_t)b * OUT_K + k) * 6;
        if (g == 0ull) {
            if (lane < 6) o[lane] = 0.f;
        } else {
            int wl = __ffs(win) - 1;
            if (lane == wl) {
                int s = (cur[0] == g) ? 0 : (cur[1] == g) ? 1 : 2;
                int c = lane + 32 * s;
                int pp = ptr[s];
                int bi = g_cbox[b][c][pp];
                const float* bx = x + ((size_t)b * NN + bi) * ROWF;
                o[0] = (float)c;
                o[1] = __uint_as_float((uint32_t)(g >> 32));
                o[2] = fminf(fmaxf(bx[0], 0.f), 1.f);
                o[3] = fminf(fmaxf(bx[1], 0.f), 1.f);
                o[4] = fminf(fmaxf(bx[2], 0.f), 1.f);
                o[5] = fminf(fmaxf(bx[3], 0.f), 1.f);
                ptr[s] = pp + 1;
                cur[s] = (ptr[s] < cnt[s]) ? g_ckey[b][c][ptr[s]] : 0ull;
            }
        }
    }
}

extern "C" void kernel_launch(void* const* d_in, const int* in_sizes, int n_in,
                              void* d_out, int out_size) {
    const float* x = (const float*)d_in[0];
    float* out = (float*)d_out;
    (void)in_sizes; (void)n_in; (void)out_size;

    dim3 g1(NN / 16, BB);
    iou_mask_kernel<<<g1, 256>>>(x);
    dim3 g2(CC, BB);
    nms_kernel<<<g2, 256>>>(x);
    topk_kernel<<<BB, 32>>>(x, out);
}

// round 6
// speedup vs baseline: 1.1862x; 1.1862x over previous
#include <cuda_runtime.h>
#include <stdint.h>

#define BB 8
#define NN 2048
#define CC 80
#define ROWF 84          // floats per box row: 4 box + 80 scores
#define NW 64            // uint32 words per mask row (2048/32)
#define OUT_K 200
#define SCORE_THR 0.01f
#define FULLM 0xFFFFFFFFu

// Persistent scratch (no allocations allowed)
__device__ uint32_t           g_mask[BB][NN][NW];          // 4 MB  : IoU>0.5 bitmask
__device__ unsigned long long g_ckey[BB][CC][OUT_K];       // (score_bits<<32)|~flatidx
__device__ int                g_cbox[BB][CC][OUT_K];       // original box index
__device__ int                g_ccnt[BB][CC];

// ---------------------------------------------------------------------------
// Kernel 1: IoU>0.5 bitmask. grid(NN/16, B), 256 threads. (unchanged, 45.8us)
// ---------------------------------------------------------------------------
__global__ __launch_bounds__(256) void iou_mask_kernel(const float* __restrict__ x) {
    const int b = blockIdx.y;
    const int r = threadIdx.x >> 6;        // 0..3
    const int w = threadIdx.x & 63;        // 0..63
    const int i0 = blockIdx.x * 16 + r * 4;

    __shared__ float4 sb[NN];              // 32 KB (xor-swizzled)
    __shared__ float  sa[NN];              // 8 KB

    const float* xb = x + (size_t)b * NN * ROWF;
    for (int j = threadIdx.x; j < NN; j += 256) {
        float4 v = *reinterpret_cast<const float4*>(xb + (size_t)j * ROWF);
        int pj = j ^ ((j >> 5) & 31);
        sb[pj] = v;
        sa[pj] = __fmul_rn(v.z - v.x, v.w - v.y);
    }
    __syncthreads();

    float4 bi[4]; float ai[4];
#pragma unroll
    for (int q = 0; q < 4; q++) {
        int pi = (i0 + q) ^ (((i0 + q) >> 5) & 31);
        bi[q] = sb[pi];
        ai[q] = sa[pi];
    }

    uint32_t word[4] = {0, 0, 0, 0};
    const int j0 = w * 32;
    const int m  = w & 31;
#pragma unroll 8
    for (int t = 0; t < 32; t++) {
        int pj = j0 + (t ^ m);             // swizzled: conflict-free
        float4 bj = sb[pj];
        float  aj = sa[pj];
#pragma unroll
        for (int q = 0; q < 4; q++) {
            float lx = fmaxf(bi[q].x, bj.x), ly = fmaxf(bi[q].y, bj.y);
            float rx = fminf(bi[q].z, bj.z), ry = fminf(bi[q].w, bj.w);
            float ww = fmaxf(__fadd_rn(rx, -lx), 0.f);
            float hh = fmaxf(__fadd_rn(ry, -ly), 0.f);
            float inter = __fmul_rn(ww, hh);
            float uni   = __fadd_rn(__fadd_rn(ai[q], aj), -inter);
            float lhs   = __fadd_rn(inter, inter);          // exact
            bool bit = lhs > uni;                            // == (inter/uni > 0.5)
            if (fabsf(__fadd_rn(lhs, -uni)) <= __fmul_rn(1e-6f, uni)) {
                bit = __fdiv_rn(inter, fmaxf(uni, 1e-8f)) > 0.5f;   // boundary: exact
            }
            if (bit) word[q] |= 1u << t;
        }
    }
#pragma unroll
    for (int q = 0; q < 4; q++) g_mask[b][i0 + q][w] = word[q];
}

// ---------------------------------------------------------------------------
// Kernel 2: one block (256 thr) per (class, batch).
//   Smem bitonic sort, pair-indexed passes for j>=8; j=4,2,1 folded into a
//   single in-register pass over each thread's contiguous 8-element block.
//   Then warp 0 runs bitmask NMS with alive mask in registers.
// ---------------------------------------------------------------------------
#define CSWAP(a, c, d) { if ((d) ? (v[a] < v[c]) : (v[a] > v[c])) \
                         { unsigned long long _t = v[a]; v[a] = v[c]; v[c] = _t; } }

__device__ __forceinline__ int ss(int i) { return i + (i >> 3); }  // stride-9 pad

__device__ __forceinline__ void reg_merge(unsigned long long v[8], bool d) {
    CSWAP(0,4,d) CSWAP(1,5,d) CSWAP(2,6,d) CSWAP(3,7,d)
    CSWAP(0,2,d) CSWAP(1,3,d) CSWAP(4,6,d) CSWAP(5,7,d)
    CSWAP(0,1,d) CSWAP(2,3,d) CSWAP(4,5,d) CSWAP(6,7,d)
}

__global__ __launch_bounds__(256) void nms_kernel(const float* __restrict__ x) {
    const int b = blockIdx.y, c = blockIdx.x;
    __shared__ unsigned long long sk[NN + NN / 8];          // 18 KB padded

    const int tid  = threadIdx.x;
    const int lane = tid & 31;
    const int g0   = tid * 8;
    const int base = ss(g0);                // contiguous 8-slot window
    const float* xb = x + (size_t)b * NN * ROWF;

    // ---- load 8 keys + in-register sort of each 8-block (k = 2,4,8) ----
    {
        unsigned long long v[8];
#pragma unroll
        for (int t = 0; t < 8; t++) {
            int i = g0 + t;
            uint32_t sbits = __float_as_uint(xb[(size_t)i * ROWF + 4 + c]);
            v[t] = ((unsigned long long)sbits << 32)
                 | (unsigned long long)(FULLM - (uint32_t)i);   // idx tie-break
        }
        CSWAP(0,1,true) CSWAP(2,3,false) CSWAP(4,5,true) CSWAP(6,7,false)
        CSWAP(0,2,true) CSWAP(1,3,true)  CSWAP(4,6,false) CSWAP(5,7,false)
        CSWAP(0,1,true) CSWAP(2,3,true)  CSWAP(4,5,false) CSWAP(6,7,false)
        reg_merge(v, (g0 & 8) == 0);
#pragma unroll
        for (int t = 0; t < 8; t++) sk[base + t] = v[t];
    }

    // ---- k = 16 .. 2048 ----
#pragma unroll 1
    for (int k = 16; k <= NN; k <<= 1) {
#pragma unroll 1
        for (int j = k >> 1; j >= 8; j >>= 1) {
            __syncthreads();
            const int jm1 = j - 1;
#pragma unroll
            for (int q = 0; q < 4; q++) {
                int p  = tid + 256 * q;                   // pair index 0..1023
                int i  = ((p & ~jm1) << 1) | (p & jm1);
                int ix = i + j;
                unsigned long long a  = sk[ss(i)];
                unsigned long long bv = sk[ss(ix)];
                bool desc = ((i & k) == 0);
                if (desc ? (a < bv) : (a > bv)) { sk[ss(i)] = bv; sk[ss(ix)] = a; }
            }
        }
        __syncthreads();
        // j = 4,2,1 inside own contiguous 8-block, in registers
        unsigned long long v[8];
#pragma unroll
        for (int t = 0; t < 8; t++) v[t] = sk[base + t];
        reg_merge(v, (g0 & k) == 0);
#pragma unroll
        for (int t = 0; t < 8; t++) sk[base + t] = v[t];
    }
    __syncthreads();

    if (tid >= 32) return;                  // warp 0 finishes alone

    // alive bitmask over ORIGINAL indices: lane owns words 2*lane, 2*lane+1
    uint32_t a0 = FULLM, a1 = FULLM;
    int kept = 0;
    int p = 0;
    const uint32_t* mb = &g_mask[b][0][0];

    while (p < NN && kept < OUT_K) {
        int pp = p + lane;
        unsigned long long key = (pp < NN) ? sk[ss(pp)] : 0ull;
        float s = __uint_as_float((uint32_t)(key >> 32));
        bool sok = (pp < NN) && (s > SCORE_THR);
        int oi  = (int)(FULLM - (uint32_t)(key & FULLM));
        int wrd = (oi >> 5) & 63;
        uint32_t v0 = __shfl_sync(FULLM, a0, wrd >> 1);
        uint32_t v1 = __shfl_sync(FULLM, a1, wrd >> 1);
        uint32_t av = (wrd & 1) ? v1 : v0;
        bool alive = (av >> (oi & 31)) & 1u;

        uint32_t bal_s = __ballot_sync(FULLM, sok);
        uint32_t cand  = __ballot_sync(FULLM, sok && alive);
        if (cand == 0) {
            if (bal_s != FULLM) break;      // sorted: everything later fails score too
            p += 32;
            continue;
        }
        int l  = __ffs(cand) - 1;
        int pf = p + l;
        int oif = __shfl_sync(FULLM, oi, l);
        unsigned long long keyf = __shfl_sync(FULLM, key, l);
        if (lane == 0) {
            uint32_t sbits = (uint32_t)(keyf >> 32);
            uint32_t flat  = (uint32_t)(c * NN + pf);
            g_ckey[b][c][kept] = ((unsigned long long)sbits << 32)
                               | (unsigned long long)(FULLM - flat);
            g_cbox[b][c][kept] = oif;
        }
        kept++;
        const uint32_t* __restrict__ row = mb + (size_t)oif * NW;
        a0 &= ~row[2 * lane];
        a1 &= ~row[2 * lane + 1];           // self-bit clears oif from alive
        p = pf + 1;
    }
    if (lane == 0) g_ccnt[b][c] = kept;
}

// ---------------------------------------------------------------------------
// Kernel 3: per-batch top-200 merge of 80 sorted lists. grid(B), 32 threads.
// ---------------------------------------------------------------------------
__global__ void topk_kernel(const float* __restrict__ x, float* __restrict__ out) {
    const int b = blockIdx.x;
    const int lane = threadIdx.x;

    int cnt[3]; int ptr[3]; unsigned long long cur[3];
#pragma unroll
    for (int s = 0; s < 3; s++) {
        int c = lane + 32 * s;
        if (c < CC) {
            cnt[s] = g_ccnt[b][c];
            ptr[s] = 0;
            cur[s] = (cnt[s] > 0) ? g_ckey[b][c][0] : 0ull;
        } else { cnt[s] = 0; ptr[s] = 0; cur[s] = 0ull; }
    }

    for (int k = 0; k < OUT_K; k++) {
        unsigned long long m = cur[0];
        if (cur[1] > m) m = cur[1];
        if (cur[2] > m) m = cur[2];
        unsigned long long g = m;
#pragma unroll
        for (int off = 16; off > 0; off >>= 1) {
            unsigned long long o = __shfl_xor_sync(FULLM, g, off);
            if (o > g) g = o;
        }
        uint32_t win = __ballot_sync(FULLM, (m == g) && (g != 0ull));
        float* o = out + ((size_t)b * OUT_K + k) * 6;
        if (g == 0ull) {
            if (lane < 6) o[lane] = 0.f;
        } else {
            int wl = __ffs(win) - 1;
            if (lane == wl) {
                int s = (cur[0] == g) ? 0 : (cur[1] == g) ? 1 : 2;
                int c = lane + 32 * s;
                int pp = ptr[s];
                int bi = g_cbox[b][c][pp];
                const float* bx = x + ((size_t)b * NN + bi) * ROWF;
                o[0] = (float)c;
                o[1] = __uint_as_float((uint32_t)(g >> 32));
                o[2] = fminf(fmaxf(bx[0], 0.f), 1.f);
                o[3] = fminf(fmaxf(bx[1], 0.f), 1.f);
                o[4] = fminf(fmaxf(bx[2], 0.f), 1.f);
                o[5] = fminf(fmaxf(bx[3], 0.f), 1.f);
                ptr[s] = pp + 1;
                cur[s] = (ptr[s] < cnt[s]) ? g_ckey[b][c][ptr[s]] : 0ull;
            }
        }
    }
}

extern "C" void kernel_launch(void* const* d_in, const int* in_sizes, int n_in,
                              void* d_out, int out_size) {
    const float* x = (const float*)d_in[0];
    float* out = (float*)d_out;
    (void)in_sizes; (void)n_in; (void)out_size;

    dim3 g1(NN / 16, BB);
    iou_mask_kernel<<<g1, 256>>>(x);
    dim3 g2(CC, BB);
    nms_kernel<<<g2, 256>>>(x);
    topk_kernel<<<BB, 32>>>(x, out);
}

// round 7
// speedup vs baseline: 1.1996x; 1.0113x over previous
#include <cuda_runtime.h>
#include <stdint.h>

#define BB 8
#define NN 2048
#define CC 80
#define ROWF 84          // floats per box row: 4 box + 80 scores
#define NW 64            // uint32 words per mask row (2048/32)
#define OUT_K 200
#define SCORE_THR 0.01f
#define FULLM 0xFFFFFFFFu

// Persistent scratch (no allocations allowed)
__device__ uint32_t           g_mask[BB][NN][NW];          // 4 MB  : IoU>0.5 bitmask
__device__ unsigned long long g_ckey[BB][CC][OUT_K];       // (score_bits<<32)|~flatidx
__device__ int                g_cbox[BB][CC][OUT_K];       // original box index
__device__ int                g_ccnt[BB][CC];

// ---------------------------------------------------------------------------
// Kernel 1: IoU>0.5 bitmask. grid(NN/16, B), 256 threads. (stable, 45us)
// ---------------------------------------------------------------------------
__global__ __launch_bounds__(256) void iou_mask_kernel(const float* __restrict__ x) {
    const int b = blockIdx.y;
    const int r = threadIdx.x >> 6;        // 0..3
    const int w = threadIdx.x & 63;        // 0..63
    const int i0 = blockIdx.x * 16 + r * 4;

    __shared__ float4 sb[NN];              // 32 KB (xor-swizzled)
    __shared__ float  sa[NN];              // 8 KB

    const float* xb = x + (size_t)b * NN * ROWF;
    for (int j = threadIdx.x; j < NN; j += 256) {
        float4 v = *reinterpret_cast<const float4*>(xb + (size_t)j * ROWF);
        int pj = j ^ ((j >> 5) & 31);
        sb[pj] = v;
        sa[pj] = __fmul_rn(v.z - v.x, v.w - v.y);
    }
    __syncthreads();

    float4 bi[4]; float ai[4];
#pragma unroll
    for (int q = 0; q < 4; q++) {
        int pi = (i0 + q) ^ (((i0 + q) >> 5) & 31);
        bi[q] = sb[pi];
        ai[q] = sa[pi];
    }

    uint32_t word[4] = {0, 0, 0, 0};
    const int j0 = w * 32;
    const int m  = w & 31;
#pragma unroll 8
    for (int t = 0; t < 32; t++) {
        int pj = j0 + (t ^ m);             // swizzled: conflict-free
        float4 bj = sb[pj];
        float  aj = sa[pj];
#pragma unroll
        for (int q = 0; q < 4; q++) {
            float lx = fmaxf(bi[q].x, bj.x), ly = fmaxf(bi[q].y, bj.y);
            float rx = fminf(bi[q].z, bj.z), ry = fminf(bi[q].w, bj.w);
            float ww = fmaxf(__fadd_rn(rx, -lx), 0.f);
            float hh = fmaxf(__fadd_rn(ry, -ly), 0.f);
            float inter = __fmul_rn(ww, hh);
            float uni   = __fadd_rn(__fadd_rn(ai[q], aj), -inter);
            float lhs   = __fadd_rn(inter, inter);          // exact
            bool bit = lhs > uni;                            // == (inter/uni > 0.5)
            if (fabsf(__fadd_rn(lhs, -uni)) <= __fmul_rn(1e-6f, uni)) {
                bit = __fdiv_rn(inter, fmaxf(uni, 1e-8f)) > 0.5f;   // boundary: exact
            }
            if (bit) word[q] |= 1u << t;
        }
    }
#pragma unroll
    for (int q = 0; q < 4; q++) g_mask[b][i0 + q][w] = word[q];
}

// ---------------------------------------------------------------------------
// Kernel 2: one block (256 thr) per (class, batch).
//   Smem bitonic sort (R6 structure), then warp 0 runs CHUNKED greedy NMS:
//   32 sorted positions per iteration, pairwise in-chunk suppression via
//   batched independent loads, register/ballot greedy resolve.
// ---------------------------------------------------------------------------
#define CSWAP(a, c, d) { if ((d) ? (v[a] < v[c]) : (v[a] > v[c])) \
                         { unsigned long long _t = v[a]; v[a] = v[c]; v[c] = _t; } }

__device__ __forceinline__ int ss(int i) { return i + (i >> 3); }  // stride-9 pad

__device__ __forceinline__ void reg_merge(unsigned long long v[8], bool d) {
    CSWAP(0,4,d) CSWAP(1,5,d) CSWAP(2,6,d) CSWAP(3,7,d)
    CSWAP(0,2,d) CSWAP(1,3,d) CSWAP(4,6,d) CSWAP(5,7,d)
    CSWAP(0,1,d) CSWAP(2,3,d) CSWAP(4,5,d) CSWAP(6,7,d)
}

__global__ __launch_bounds__(256) void nms_kernel(const float* __restrict__ x) {
    const int b = blockIdx.y, c = blockIdx.x;
    __shared__ unsigned long long sk[NN + NN / 8];          // 18 KB padded

    const int tid  = threadIdx.x;
    const int g0   = tid * 8;
    const int base = ss(g0);                // contiguous 8-slot window
    const float* xb = x + (size_t)b * NN * ROWF;

    // ---- load 8 keys + in-register sort of each 8-block (k = 2,4,8) ----
    {
        unsigned long long v[8];
#pragma unroll
        for (int t = 0; t < 8; t++) {
            int i = g0 + t;
            uint32_t sbits = __float_as_uint(xb[(size_t)i * ROWF + 4 + c]);
            v[t] = ((unsigned long long)sbits << 32)
                 | (unsigned long long)(FULLM - (uint32_t)i);   // idx tie-break
        }
        CSWAP(0,1,true) CSWAP(2,3,false) CSWAP(4,5,true) CSWAP(6,7,false)
        CSWAP(0,2,true) CSWAP(1,3,true)  CSWAP(4,6,false) CSWAP(5,7,false)
        CSWAP(0,1,true) CSWAP(2,3,true)  CSWAP(4,5,false) CSWAP(6,7,false)
        reg_merge(v, (g0 & 8) == 0);
#pragma unroll
        for (int t = 0; t < 8; t++) sk[base + t] = v[t];
    }

    // ---- k = 16 .. 2048 ----
#pragma unroll 1
    for (int k = 16; k <= NN; k <<= 1) {
#pragma unroll 1
        for (int j = k >> 1; j >= 8; j >>= 1) {
            __syncthreads();
            const int jm1 = j - 1;
#pragma unroll
            for (int q = 0; q < 4; q++) {
                int p  = tid + 256 * q;                   // pair index 0..1023
                int i  = ((p & ~jm1) << 1) | (p & jm1);
                int ix = i + j;
                unsigned long long a  = sk[ss(i)];
                unsigned long long bv = sk[ss(ix)];
                bool desc = ((i & k) == 0);
                if (desc ? (a < bv) : (a > bv)) { sk[ss(i)] = bv; sk[ss(ix)] = a; }
            }
        }
        __syncthreads();
        // j = 4,2,1 inside own contiguous 8-block, in registers
        unsigned long long v[8];
#pragma unroll
        for (int t = 0; t < 8; t++) v[t] = sk[base + t];
        reg_merge(v, (g0 & k) == 0);
#pragma unroll
        for (int t = 0; t < 8; t++) sk[base + t] = v[t];
    }
    __syncthreads();

    if (tid >= 32) return;                  // warp 0 finishes alone
    const int lane = tid;

    // alive bitmask over ORIGINAL indices: lane owns words 2*lane, 2*lane+1
    uint32_t a0 = FULLM, a1 = FULLM;
    int kept = 0;
    int p = 0;
    const uint32_t* mb = &g_mask[b][0][0];

    while (p < NN && kept < OUT_K) {
        const int pp = p + lane;
        unsigned long long key = sk[ss(pp)];
        float s = __uint_as_float((uint32_t)(key >> 32));
        bool sok = (s > SCORE_THR);
        int oi  = (int)(FULLM - (uint32_t)(key & FULLM));
        int wrd = (oi >> 5) & 63;
        uint32_t v0 = __shfl_sync(FULLM, a0, wrd >> 1);
        uint32_t v1 = __shfl_sync(FULLM, a1, wrd >> 1);
        uint32_t av = (wrd & 1) ? v1 : v0;
        bool alive = (av >> (oi & 31)) & 1u;

        uint32_t bal_s = __ballot_sync(FULLM, sok);
        uint32_t cand  = __ballot_sync(FULLM, sok && alive);

        if (cand) {
            // pairwise: which earlier IN-CHUNK candidates suppress me?
            // independent loads (oi of lane i read from smem keys) -> MLP
            uint32_t sup = 0;
            if (sok && alive) {
                uint32_t mm = cand & ((1u << lane) - 1u);
                while (mm) {
                    int i = __ffs(mm) - 1; mm &= mm - 1;
                    int oii = (int)(FULLM - (uint32_t)(sk[ss(p + i)] & FULLM));
                    uint32_t wv = __ldg(mb + (size_t)oii * NW + (oi >> 5));
                    sup |= ((wv >> (oi & 31)) & 1u) << i;
                }
            }
            // greedy resolve within chunk (register/ballot only)
            uint32_t keptm = 0, rem = cand;
            const int room = OUT_K - kept;
            while (rem && (int)__popc(keptm) < room) {
                int i = __ffs(rem) - 1;
                keptm |= 1u << i;
                rem   &= ~(1u << i);
                uint32_t supby = __ballot_sync(FULLM, (sup >> i) & 1u);
                rem &= ~supby;
            }
            // emit kept candidates (order = lane order = sorted order)
            if ((keptm >> lane) & 1u) {
                int slot = kept + __popc(keptm & ((1u << lane) - 1u));
                uint32_t flat = (uint32_t)(c * NN + pp);
                g_ckey[b][c][slot] = ((unsigned long long)(uint32_t)(key >> 32) << 32)
                                   | (unsigned long long)(FULLM - flat);
                g_cbox[b][c][slot] = oi;
            }
            // apply kept rows to alive mask (batched independent loads)
            uint32_t am = keptm;
            while (am) {
                int i = __ffs(am) - 1; am &= am - 1;
                int oii = (int)(FULLM - (uint32_t)(sk[ss(p + i)] & FULLM));
                const uint32_t* __restrict__ row = mb + (size_t)oii * NW;
                a0 &= ~row[2 * lane];
                a1 &= ~row[2 * lane + 1];
            }
            kept += __popc(keptm);
        }
        if (bal_s != FULLM) break;          // sorted: everything later fails score
        p += 32;
    }
    if (lane == 0) g_ccnt[b][c] = kept;
}

// ---------------------------------------------------------------------------
// Kernel 3: per-batch top-200 via radix-select on score bits + 512 bitonic.
//   grid(B), 256 threads. No serial 200-round dependency chain.
// ---------------------------------------------------------------------------
__global__ __launch_bounds__(256) void topk_kernel(const float* __restrict__ x,
                                                   float* __restrict__ out) {
    const int b = blockIdx.x;
    const int tid = threadIdx.x;
    __shared__ int s_cnt[CC];
    __shared__ int s_hist[256];
    __shared__ int s_scan[256];
    __shared__ unsigned long long s_key[512];
    __shared__ uint32_t s_pay[512];
    __shared__ int s_T, s_cut, s_num;

    if (tid < CC) s_cnt[tid] = g_ccnt[b][tid];
    __syncthreads();
    if (tid == 0) {
        int t = 0;
        for (int c = 0; c < CC; c++) t += s_cnt[c];
        s_T = t;
    }
    __syncthreads();
    const int T = s_T;
    int k = (T < OUT_K) ? T : OUT_K;
    const int kinit = k;

    uint32_t S = 0;        // high-32 cutoff, built MSB-byte down
    if (k > 0) {
#pragma unroll 1
        for (int lev = 3; lev >= 0; lev--) {
            s_hist[tid] = 0;
            __syncthreads();
            for (int idx = tid; idx < CC * OUT_K; idx += 256) {
                int c = idx / OUT_K, slot = idx - c * OUT_K;
                if (slot < s_cnt[c]) {
                    uint32_t hi = (uint32_t)(g_ckey[b][c][slot] >> 32);
                    bool match = (lev == 3) ? true
                               : ((hi >> ((lev + 1) * 8)) == (S >> ((lev + 1) * 8)));
                    if (match) atomicAdd(&s_hist[(hi >> (lev * 8)) & 255], 1);
                }
            }
            __syncthreads();
            // suffix sums: s_scan[d] = sum_{d' >= d} hist[d']
            int h = s_hist[tid];
            s_scan[tid] = h;
            __syncthreads();
#pragma unroll
            for (int off = 1; off < 256; off <<= 1) {
                int v2 = (tid + off < 256) ? s_scan[tid + off] : 0;
                __syncthreads();
                s_scan[tid] += v2;
                __syncthreads();
            }
            int cnt_gt = s_scan[tid] - h;
            if (cnt_gt < k && k <= cnt_gt + h) { s_cut = tid; s_num = cnt_gt; }
            __syncthreads();
            S |= ((uint32_t)s_cut) << (lev * 8);
            k -= s_num;
            __syncthreads();
        }
    }

    // gather keys with high32 >= S  (count: (#>S) + (#==S) >= kinit, small)
    if (tid == 0) s_num = 0;
    __syncthreads();
    if (kinit > 0) {
        for (int idx = tid; idx < CC * OUT_K; idx += 256) {
            int c = idx / OUT_K, slot = idx - c * OUT_K;
            if (slot < s_cnt[c]) {
                unsigned long long key = g_ckey[b][c][slot];
                if ((uint32_t)(key >> 32) >= S) {
                    int p_ = atomicAdd(&s_num, 1);
                    if (p_ < 512) { s_key[p_] = key; s_pay[p_] = (uint32_t)idx; }
                }
            }
        }
    }
    __syncthreads();
    int num = s_num < 512 ? s_num : 512;
    for (int i2 = num + tid; i2 < 512; i2 += 256) { s_key[i2] = 0ull; s_pay[i2] = 0u; }
    __syncthreads();

    // bitonic sort 512 desc (keys unique -> deterministic; ties by ~flat low32)
#pragma unroll 1
    for (int kk = 2; kk <= 512; kk <<= 1) {
#pragma unroll 1
        for (int j = kk >> 1; j > 0; j >>= 1) {
            int i2 = ((tid & ~(j - 1)) << 1) | (tid & (j - 1));
            int ix = i2 + j;
            unsigned long long a = s_key[i2], bb2 = s_key[ix];
            bool desc2 = ((i2 & kk) == 0);
            if (desc2 ? (a < bb2) : (a > bb2)) {
                s_key[i2] = bb2; s_key[ix] = a;
                uint32_t tp = s_pay[i2]; s_pay[i2] = s_pay[ix]; s_pay[ix] = tp;
            }
            __syncthreads();
        }
    }

    // emit rows
    if (tid < OUT_K) {
        float* o = out + ((size_t)b * OUT_K + tid) * 6;
        if (tid < kinit) {
            unsigned long long key = s_key[tid];
            uint32_t pay = s_pay[tid];
            int c = pay / OUT_K, slot = pay - c * OUT_K;
            int bi = g_cbox[b][c][slot];
            const float* bx = x + ((size_t)b * NN + bi) * ROWF;
            o[0] = (float)c;
            o[1] = __uint_as_float((uint32_t)(key >> 32));
            o[2] = fminf(fmaxf(bx[0], 0.f), 1.f);
            o[3] = fminf(fmaxf(bx[1], 0.f), 1.f);
            o[4] = fminf(fmaxf(bx[2], 0.f), 1.f);
            o[5] = fminf(fmaxf(bx[3], 0.f), 1.f);
        } else {
            o[0] = o[1] = o[2] = o[3] = o[4] = o[5] = 0.f;
        }
    }
}

extern "C" void kernel_launch(void* const* d_in, const int* in_sizes, int n_in,
                              void* d_out, int out_size) {
    const float* x = (const float*)d_in[0];
    float* out = (float*)d_out;
    (void)in_sizes; (void)n_in; (void)out_size;

    dim3 g1(NN / 16, BB);
    iou_mask_kernel<<<g1, 256>>>(x);
    dim3 g2(CC, BB);
    nms_kernel<<<g2, 256>>>(x);
    topk_kernel<<<BB, 256>>>(x, out);
}

// round 11
// speedup vs baseline: 1.2937x; 1.0784x over previous
#include <cuda_runtime.h>
#include <stdint.h>

#define BB 8
#define NN 2048
#define CC 80
#define ROWF 84          // floats per box row: 4 box + 80 scores
#define NW 64            // uint32 words per mask row (2048/32)
#define OUT_K 200
#define SCORE_THR 0.01f
#define FULLM 0xFFFFFFFFu

// Persistent scratch (no allocations allowed)
__device__ uint32_t           g_mask[BB][NN][NW];          // 4 MB  : IoU>0.5 bitmask
__device__ unsigned long long g_ckey[BB][CC][OUT_K];       // (score_bits<<32)|~flatidx
__device__ int                g_cbox[BB][CC][OUT_K];       // original box index
__device__ int                g_ccnt[BB][CC];

// ---------------------------------------------------------------------------
// Kernel 1: IoU>0.5 bitmask. grid(NN/16, B), 256 threads. (stable, 45us)
// ---------------------------------------------------------------------------
__global__ __launch_bounds__(256) void iou_mask_kernel(const float* __restrict__ x) {
    const int b = blockIdx.y;
    const int r = threadIdx.x >> 6;        // 0..3
    const int w = threadIdx.x & 63;        // 0..63
    const int i0 = blockIdx.x * 16 + r * 4;

    __shared__ float4 sb[NN];              // 32 KB (xor-swizzled)
    __shared__ float  sa[NN];              // 8 KB

    const float* xb = x + (size_t)b * NN * ROWF;
    for (int j = threadIdx.x; j < NN; j += 256) {
        float4 v = *reinterpret_cast<const float4*>(xb + (size_t)j * ROWF);
        int pj = j ^ ((j >> 5) & 31);
        sb[pj] = v;
        sa[pj] = __fmul_rn(v.z - v.x, v.w - v.y);
    }
    __syncthreads();

    float4 bi[4]; float ai[4];
#pragma unroll
    for (int q = 0; q < 4; q++) {
        int pi = (i0 + q) ^ (((i0 + q) >> 5) & 31);
        bi[q] = sb[pi];
        ai[q] = sa[pi];
    }

    uint32_t word[4] = {0, 0, 0, 0};
    const int j0 = w * 32;
    const int m  = w & 31;
#pragma unroll 8
    for (int t = 0; t < 32; t++) {
        int pj = j0 + (t ^ m);             // swizzled: conflict-free
        float4 bj = sb[pj];
        float  aj = sa[pj];
#pragma unroll
        for (int q = 0; q < 4; q++) {
            float lx = fmaxf(bi[q].x, bj.x), ly = fmaxf(bi[q].y, bj.y);
            float rx = fminf(bi[q].z, bj.z), ry = fminf(bi[q].w, bj.w);
            float ww = fmaxf(__fadd_rn(rx, -lx), 0.f);
            float hh = fmaxf(__fadd_rn(ry, -ly), 0.f);
            float inter = __fmul_rn(ww, hh);
            float uni   = __fadd_rn(__fadd_rn(ai[q], aj), -inter);
            float lhs   = __fadd_rn(inter, inter);          // exact
            bool bit = lhs > uni;                            // == (inter/uni > 0.5)
            if (fabsf(__fadd_rn(lhs, -uni)) <= __fmul_rn(1e-6f, uni)) {
                bit = __fdiv_rn(inter, fmaxf(uni, 1e-8f)) > 0.5f;   // boundary: exact
            }
            if (bit) word[q] |= 1u << t;
        }
    }
#pragma unroll
    for (int q = 0; q < 4; q++) g_mask[b][i0 + q][w] = word[q];
}

// ---------------------------------------------------------------------------
// Kernel 2: one block (256 thr) per (class, batch).
//   R4-style plain smem bitonic sort (measured best) + chunked greedy NMS.
// ---------------------------------------------------------------------------
__global__ __launch_bounds__(256) void nms_kernel(const float* __restrict__ x) {
    const int b = blockIdx.y, c = blockIdx.x;
    __shared__ unsigned long long sk[NN];                   // 16 KB

    const int tid = threadIdx.x;
    const float* xb = x + (size_t)b * NN * ROWF;
    for (int i = tid; i < NN; i += 256) {
        uint32_t sbits = __float_as_uint(xb[(size_t)i * ROWF + 4 + c]);  // >= 0
        sk[i] = ((unsigned long long)sbits << 32)
              | (unsigned long long)(FULLM - (uint32_t)i);  // idx tie-break
    }
    __syncthreads();

    // Bitonic sort, descending (plain: conflict-free 64-bit consecutive access)
    for (int k = 2; k <= NN; k <<= 1) {
        for (int j = k >> 1; j > 0; j >>= 1) {
            for (int i = tid; i < NN; i += 256) {
                int ixj = i ^ j;
                if (ixj > i) {
                    unsigned long long a = sk[i], bv = sk[ixj];
                    bool desc = ((i & k) == 0);
                    if (desc ? (a < bv) : (a > bv)) { sk[i] = bv; sk[ixj] = a; }
                }
            }
            __syncthreads();
        }
    }

    if (tid >= 32) return;                  // warp 0 finishes alone
    const int lane = tid;

    // alive bitmask over ORIGINAL indices: lane owns words 2*lane, 2*lane+1
    uint32_t a0 = FULLM, a1 = FULLM;
    int kept = 0;
    int p = 0;
    const uint32_t* mb = &g_mask[b][0][0];

    while (p < NN && kept < OUT_K) {
        const int pp = p + lane;
        unsigned long long key = sk[pp];
        float s = __uint_as_float((uint32_t)(key >> 32));
        bool sok = (s > SCORE_THR);
        int oi  = (int)(FULLM - (uint32_t)(key & FULLM));
        int wrd = (oi >> 5) & 63;
        uint32_t v0 = __shfl_sync(FULLM, a0, wrd >> 1);
        uint32_t v1 = __shfl_sync(FULLM, a1, wrd >> 1);
        uint32_t av = (wrd & 1) ? v1 : v0;
        bool alive = (av >> (oi & 31)) & 1u;

        uint32_t bal_s = __ballot_sync(FULLM, sok);
        uint32_t cand  = __ballot_sync(FULLM, sok && alive);

        if (cand) {
            // which earlier IN-CHUNK candidates suppress me? (independent loads)
            uint32_t sup = 0;
            if (sok && alive) {
                uint32_t mm = cand & ((1u << lane) - 1u);
                while (mm) {
                    int i = __ffs(mm) - 1; mm &= mm - 1;
                    int oii = (int)(FULLM - (uint32_t)(sk[p + i] & FULLM));
                    uint32_t wv = __ldg(mb + (size_t)oii * NW + (oi >> 5));
                    sup |= ((wv >> (oi & 31)) & 1u) << i;
                }
            }
            // greedy resolve within chunk (register/ballot only)
            uint32_t keptm = 0, rem = cand;
            const int room = OUT_K - kept;
            while (rem && (int)__popc(keptm) < room) {
                int i = __ffs(rem) - 1;
                keptm |= 1u << i;
                rem   &= ~(1u << i);
                uint32_t supby = __ballot_sync(FULLM, (sup >> i) & 1u);
                rem &= ~supby;
            }
            // emit kept candidates (sorted order preserved)
            if ((keptm >> lane) & 1u) {
                int slot = kept + __popc(keptm & ((1u << lane) - 1u));
                uint32_t flat = (uint32_t)(c * NN + pp);
                g_ckey[b][c][slot] = ((unsigned long long)(uint32_t)(key >> 32) << 32)
                                   | (unsigned long long)(FULLM - flat);
                g_cbox[b][c][slot] = oi;
            }
            // apply kept rows to alive mask (batched independent loads)
            uint32_t am = keptm;
            while (am) {
                int i = __ffs(am) - 1; am &= am - 1;
                int oii = (int)(FULLM - (uint32_t)(sk[p + i] & FULLM));
                const uint32_t* __restrict__ row = mb + (size_t)oii * NW;
                a0 &= ~row[2 * lane];
                a1 &= ~row[2 * lane + 1];
            }
            kept += __popc(keptm);
        }
        if (bal_s != FULLM) break;          // sorted: everything later fails score
        p += 32;
    }
    if (lane == 0) g_ccnt[b][c] = kept;
}

// ---------------------------------------------------------------------------
// Kernel 3: per-batch top-200 via 3-level radix-select (24-bit prefix) +
//   512 bitonic. Level 3 uses register counters (high byte in {0x3C..0x3F}).
// ---------------------------------------------------------------------------
__global__ __launch_bounds__(256) void topk_kernel(const float* __restrict__ x,
                                                   float* __restrict__ out) {
    const int b = blockIdx.x;
    const int tid = threadIdx.x;
    __shared__ int s_cnt[CC];
    __shared__ int s_hist[256];
    __shared__ int s_scan[256];
    __shared__ unsigned long long s_key[512];
    __shared__ uint32_t s_pay[512];
    __shared__ int s_T, s_cut, s_num;

    if (tid == 0) s_T = 0;
    if (tid < CC) s_cnt[tid] = g_ccnt[b][tid];
    __syncthreads();
    if (tid < CC) atomicAdd(&s_T, s_cnt[tid]);
    __syncthreads();
    const int T = s_T;
    int k = (T < OUT_K) ? T : OUT_K;
    const int kinit = k;

    uint32_t S = 0;        // cutoff prefix, built MSB-byte down (3 levels)
    if (k > 0) {
#pragma unroll 1
        for (int lev = 3; lev >= 1; lev--) {
            s_hist[tid] = 0;
            __syncthreads();
            if (lev == 3) {
                // high byte of valid scores is 0x3C..0x3F: register counters
                int c0 = 0, c1 = 0, c2 = 0, c3 = 0;
                for (int idx = tid; idx < CC * OUT_K; idx += 256) {
                    int c = idx / OUT_K, slot = idx - c * OUT_K;
                    if (slot < s_cnt[c]) {
                        uint32_t d = ((uint32_t)(g_ckey[b][c][slot] >> 56)) - 0x3Cu;
                        c0 += (d == 0); c1 += (d == 1); c2 += (d == 2); c3 += (d == 3);
                    }
                }
                if (c0) atomicAdd(&s_hist[0x3C], c0);
                if (c1) atomicAdd(&s_hist[0x3D], c1);
                if (c2) atomicAdd(&s_hist[0x3E], c2);
                if (c3) atomicAdd(&s_hist[0x3F], c3);
            } else {
                for (int idx = tid; idx < CC * OUT_K; idx += 256) {
                    int c = idx / OUT_K, slot = idx - c * OUT_K;
                    if (slot < s_cnt[c]) {
                        uint32_t hi = (uint32_t)(g_ckey[b][c][slot] >> 32);
                        if ((hi >> ((lev + 1) * 8)) == (S >> ((lev + 1) * 8)))
                            atomicAdd(&s_hist[(hi >> (lev * 8)) & 255], 1);
                    }
                }
            }
            __syncthreads();
            // suffix sums: s_scan[d] = sum_{d' >= d} hist[d']
            int h = s_hist[tid];
            s_scan[tid] = h;
            __syncthreads();
#pragma unroll
            for (int off = 1; off < 256; off <<= 1) {
                int v2 = (tid + off < 256) ? s_scan[tid + off] : 0;
                __syncthreads();
                s_scan[tid] += v2;
                __syncthreads();
            }
            int cnt_gt = s_scan[tid] - h;
            if (cnt_gt < k && k <= cnt_gt + h) { s_cut = tid; s_num = cnt_gt; }
            __syncthreads();
            S |= ((uint32_t)s_cut) << (lev * 8);
            k -= s_num;
            __syncthreads();
        }
    }

    // gather keys with high32 >= S (24-bit cutoff prefix, low byte 0):
    // count = (# above prefix) + (# sharing prefix) ~ <= ~220 for this data
    if (tid == 0) s_num = 0;
    __syncthreads();
    if (kinit > 0) {
        for (int idx = tid; idx < CC * OUT_K; idx += 256) {
            int c = idx / OUT_K, slot = idx - c * OUT_K;
            if (slot < s_cnt[c]) {
                unsigned long long key = g_ckey[b][c][slot];
                if ((uint32_t)(key >> 32) >= S) {
                    int p_ = atomicAdd(&s_num, 1);
                    if (p_ < 512) { s_key[p_] = key; s_pay[p_] = (uint32_t)idx; }
                }
            }
        }
    }
    __syncthreads();
    int num = s_num < 512 ? s_num : 512;
    for (int i2 = num + tid; i2 < 512; i2 += 256) { s_key[i2] = 0ull; s_pay[i2] = 0u; }
    __syncthreads();

    // bitonic sort 512 desc (keys unique -> deterministic; ties by ~flat low32)
#pragma unroll 1
    for (int kk = 2; kk <= 512; kk <<= 1) {
#pragma unroll 1
        for (int j = kk >> 1; j > 0; j >>= 1) {
            int i2 = ((tid & ~(j - 1)) << 1) | (tid & (j - 1));
            int ix = i2 + j;
            unsigned long long a = s_key[i2], bb2 = s_key[ix];
            bool desc2 = ((i2 & kk) == 0);
            if (desc2 ? (a < bb2) : (a > bb2)) {
                s_key[i2] = bb2; s_key[ix] = a;
                uint32_t tp = s_pay[i2]; s_pay[i2] = s_pay[ix]; s_pay[ix] = tp;
            }
            __syncthreads();
        }
    }

    // emit rows
    if (tid < OUT_K) {
        float* o = out + ((size_t)b * OUT_K + tid) * 6;
        if (tid < kinit) {
            unsigned long long key = s_key[tid];
            uint32_t pay = s_pay[tid];
            int c = pay / OUT_K, slot = pay - c * OUT_K;
            int bi = g_cbox[b][c][slot];
            const float* bx = x + ((size_t)b * NN + bi) * ROWF;
            o[0] = (float)c;
            o[1] = __uint_as_float((uint32_t)(key >> 32));
            o[2] = fminf(fmaxf(bx[0], 0.f), 1.f);
            o[3] = fminf(fmaxf(bx[1], 0.f), 1.f);
            o[4] = fminf(fmaxf(bx[2], 0.f), 1.f);
            o[5] = fminf(fmaxf(bx[3], 0.f), 1.f);
        } else {
            o[0] = o[1] = o[2] = o[3] = o[4] = o[5] = 0.f;
        }
    }
}

extern "C" void kernel_launch(void* const* d_in, const int* in_sizes, int n_in,
                              void* d_out, int out_size) {
    const float* x = (const float*)d_in[0];
    float* out = (float*)d_out;
    (void)in_sizes; (void)n_in; (void)out_size;

    dim3 g1(NN / 16, BB);
    iou_mask_kernel<<<g1, 256>>>(x);
    dim3 g2(CC, BB);
    nms_kernel<<<g2, 256>>>(x);
    topk_kernel<<<BB, 256>>>(x, out);
}

// round 12
// speedup vs baseline: 1.4677x; 1.1345x over previous
#include <cuda_runtime.h>
#include <stdint.h>

#define BB 8
#define NN 2048
#define CC 80
#define ROWF 84          // floats per box row: 4 box + 80 scores
#define NW 64            // uint32 words per mask row (2048/32)
#define OUT_K 200
#define SCORE_THR 0.01f
#define FULLM 0xFFFFFFFFu
#define MSEL 768         // selection rank for the NMS batch
#define MCAP 1024        // batch capacity (power of two, sorted size)

// Persistent scratch (no allocations allowed)
__device__ uint32_t           g_mask[BB][NN][NW];          // 4 MB  : IoU>0.5 bitmask
__device__ unsigned long long g_ckey[BB][CC][OUT_K];       // (score_bits<<32)|~flatidx
__device__ int                g_cbox[BB][CC][OUT_K];       // original box index
__device__ int                g_ccnt[BB][CC];

// ---------------------------------------------------------------------------
// Kernel 1: IoU>0.5 bitmask. grid(NN/16, B), 256 threads. (stable, 45us)
// ---------------------------------------------------------------------------
__global__ __launch_bounds__(256) void iou_mask_kernel(const float* __restrict__ x) {
    const int b = blockIdx.y;
    const int r = threadIdx.x >> 6;        // 0..3
    const int w = threadIdx.x & 63;        // 0..63
    const int i0 = blockIdx.x * 16 + r * 4;

    __shared__ float4 sb[NN];              // 32 KB (xor-swizzled)
    __shared__ float  sa[NN];              // 8 KB

    const float* xb = x + (size_t)b * NN * ROWF;
    for (int j = threadIdx.x; j < NN; j += 256) {
        float4 v = *reinterpret_cast<const float4*>(xb + (size_t)j * ROWF);
        int pj = j ^ ((j >> 5) & 31);
        sb[pj] = v;
        sa[pj] = __fmul_rn(v.z - v.x, v.w - v.y);
    }
    __syncthreads();

    float4 bi[4]; float ai[4];
#pragma unroll
    for (int q = 0; q < 4; q++) {
        int pi = (i0 + q) ^ (((i0 + q) >> 5) & 31);
        bi[q] = sb[pi];
        ai[q] = sa[pi];
    }

    uint32_t word[4] = {0, 0, 0, 0};
    const int j0 = w * 32;
    const int m  = w & 31;
#pragma unroll 8
    for (int t = 0; t < 32; t++) {
        int pj = j0 + (t ^ m);             // swizzled: conflict-free
        float4 bj = sb[pj];
        float  aj = sa[pj];
#pragma unroll
        for (int q = 0; q < 4; q++) {
            float lx = fmaxf(bi[q].x, bj.x), ly = fmaxf(bi[q].y, bj.y);
            float rx = fminf(bi[q].z, bj.z), ry = fminf(bi[q].w, bj.w);
            float ww = fmaxf(__fadd_rn(rx, -lx), 0.f);
            float hh = fmaxf(__fadd_rn(ry, -ly), 0.f);
            float inter = __fmul_rn(ww, hh);
            float uni   = __fadd_rn(__fadd_rn(ai[q], aj), -inter);
            float lhs   = __fadd_rn(inter, inter);          // exact
            bool bit = lhs > uni;                            // == (inter/uni > 0.5)
            if (fabsf(__fadd_rn(lhs, -uni)) <= __fmul_rn(1e-6f, uni)) {
                bit = __fdiv_rn(inter, fmaxf(uni, 1e-8f)) > 0.5f;   // boundary: exact
            }
            if (bit) word[q] |= 1u << t;
        }
    }
#pragma unroll
    for (int q = 0; q < 4; q++) g_mask[b][i0 + q][w] = word[q];
}

// ---------------------------------------------------------------------------
// Warp-0 chunked greedy NMS over a descending-sorted key array.
// Returns kept count; emits g_ckey/g_cbox. All 32 lanes must call.
// ---------------------------------------------------------------------------
__device__ __forceinline__ int nms_scan(const unsigned long long* __restrict__ arr,
                                        int len, int b, int c,
                                        const uint32_t* __restrict__ mb, int lane) {
    uint32_t a0 = FULLM, a1 = FULLM;     // alive mask over ORIGINAL indices
    int kept = 0;
    int p = 0;
    while (p < len && kept < OUT_K) {
        const int pp = p + lane;
        unsigned long long key = arr[pp];
        float s = __uint_as_float((uint32_t)(key >> 32));
        bool sok = (s > SCORE_THR);
        int oi  = (int)(FULLM - (uint32_t)(key & FULLM));
        int wrd = (oi >> 5) & 63;
        uint32_t v0 = __shfl_sync(FULLM, a0, wrd >> 1);
        uint32_t v1 = __shfl_sync(FULLM, a1, wrd >> 1);
        uint32_t av = (wrd & 1) ? v1 : v0;
        bool alive = (av >> (oi & 31)) & 1u;

        uint32_t bal_s = __ballot_sync(FULLM, sok);
        uint32_t cand  = __ballot_sync(FULLM, sok && alive);

        if (cand) {
            // which earlier in-chunk candidates suppress me? (independent loads)
            uint32_t sup = 0;
            if (sok && alive) {
                uint32_t mm = cand & ((1u << lane) - 1u);
                while (mm) {
                    int i = __ffs(mm) - 1; mm &= mm - 1;
                    int oii = (int)(FULLM - (uint32_t)(arr[p + i] & FULLM));
                    uint32_t wv = __ldg(mb + (size_t)oii * NW + (oi >> 5));
                    sup |= ((wv >> (oi & 31)) & 1u) << i;
                }
            }
            // greedy resolve within chunk (register/ballot only)
            uint32_t keptm = 0, rem = cand;
            const int room = OUT_K - kept;
            while (rem && (int)__popc(keptm) < room) {
                int i = __ffs(rem) - 1;
                keptm |= 1u << i;
                rem   &= ~(1u << i);
                uint32_t supby = __ballot_sync(FULLM, (sup >> i) & 1u);
                rem &= ~supby;
            }
            // emit kept candidates (sorted order preserved)
            if ((keptm >> lane) & 1u) {
                int slot = kept + __popc(keptm & ((1u << lane) - 1u));
                uint32_t flat = (uint32_t)(c * NN + pp);
                g_ckey[b][c][slot] = (key & 0xFFFFFFFF00000000ull)
                                   | (unsigned long long)(FULLM - flat);
                g_cbox[b][c][slot] = oi;
            }
            // apply kept rows to alive mask (batched independent loads)
            uint32_t am = keptm;
            while (am) {
                int i = __ffs(am) - 1; am &= am - 1;
                int oii = (int)(FULLM - (uint32_t)(arr[p + i] & FULLM));
                const uint32_t* __restrict__ row = mb + (size_t)oii * NW;
                a0 &= ~row[2 * lane];
                a1 &= ~row[2 * lane + 1];
            }
            kept += __popc(keptm);
        }
        if (bal_s != FULLM) break;          // sorted: everything later fails score
        p += 32;
    }
    return kept;
}

// ---------------------------------------------------------------------------
// Kernel 2: one block (256 thr) per (class, batch).
//   Exact top-MSEL selection (2-level byte radix on score bits) ->
//   1024-wide bitonic sort of the batch -> chunked NMS.
//   Exact fallback to full 2048 sort if batch proves insufficient.
// ---------------------------------------------------------------------------
__global__ __launch_bounds__(256) void nms_kernel(const float* __restrict__ x) {
    const int b = blockIdx.y, c = blockIdx.x;
    __shared__ unsigned long long sk[NN];       // 16 KB: all keys (unsorted)
    __shared__ unsigned long long sg[MCAP];     // 8 KB : selected batch
    __shared__ int s_hist[256];
    __shared__ int s_scan[256];
    __shared__ int s_Tthr, s_num, s_cut, s_rem, s_kept;

    const int tid = threadIdx.x;
    const float* xb = x + (size_t)b * NN * ROWF;
    const uint32_t* mb = &g_mask[b][0][0];
    const uint32_t THR_BITS = __float_as_uint(SCORE_THR);

    if (tid == 0) { s_Tthr = 0; s_num = 0; }
    s_hist[tid] = 0;
    __syncthreads();

    // ---- load keys + level-1 histogram (top byte of score bits) ----
    int mythr = 0;
    for (int i = tid; i < NN; i += 256) {
        uint32_t sbits = __float_as_uint(xb[(size_t)i * ROWF + 4 + c]);  // >= 0
        sk[i] = ((unsigned long long)sbits << 32)
              | (unsigned long long)(FULLM - (uint32_t)i);  // idx tie-break
        mythr += (sbits > THR_BITS);
        atomicAdd(&s_hist[sbits >> 24], 1);
    }
    if (mythr) atomicAdd(&s_Tthr, mythr);
    __syncthreads();

    // ---- suffix scan level 1: find byte3 bin containing rank MSEL ----
    int h = s_hist[tid];
    s_scan[tid] = h;
    __syncthreads();
#pragma unroll
    for (int off = 1; off < 256; off <<= 1) {
        int v2 = (tid + off < 256) ? s_scan[tid + off] : 0;
        __syncthreads();
        s_scan[tid] += v2;
        __syncthreads();
    }
    {
        int cnt_gt = s_scan[tid] - h;
        if (cnt_gt < MSEL && MSEL <= cnt_gt + h) { s_cut = tid; s_rem = MSEL - cnt_gt; }
    }
    __syncthreads();
    const uint32_t b3 = (uint32_t)s_cut;
    const int k2 = s_rem;
    s_hist[tid] = 0;
    __syncthreads();

    // ---- level-2 histogram (byte2) within byte3 == b3 ----
    for (int i = tid; i < NN; i += 256) {
        unsigned long long key = sk[i];
        if ((uint32_t)(key >> 56) == b3)
            atomicAdd(&s_hist[(int)((key >> 48) & 255)], 1);
    }
    __syncthreads();
    h = s_hist[tid];
    s_scan[tid] = h;
    __syncthreads();
#pragma unroll
    for (int off = 1; off < 256; off <<= 1) {
        int v2 = (tid + off < 256) ? s_scan[tid + off] : 0;
        __syncthreads();
        s_scan[tid] += v2;
        __syncthreads();
    }
    {
        int cnt_gt = s_scan[tid] - h;
        if (cnt_gt < k2 && k2 <= cnt_gt + h) s_cut = tid;
    }
    __syncthreads();
    const uint32_t S16 = (b3 << 8) | (uint32_t)s_cut;   // 16-bit cutoff prefix

    // ---- gather batch: prefix >= S16 AND score > THR ----
    for (int i = tid; i < NN; i += 256) {
        unsigned long long key = sk[i];
        uint32_t sbits = (uint32_t)(key >> 32);
        if ((sbits >> 16) >= S16 && sbits > THR_BITS) {
            int p_ = atomicAdd(&s_num, 1);
            if (p_ < MCAP) sg[p_] = key;
        }
    }
    __syncthreads();
    const int G = s_num;
    const int Tthr = s_Tthr;

    if (G <= MCAP) {
        for (int i = G + tid; i < MCAP; i += 256) sg[i] = 0ull;   // pad

        // ---- bitonic sort MCAP=1024 descending, pair-indexed ----
#pragma unroll 1
        for (int k = 2; k <= MCAP; k <<= 1) {
#pragma unroll 1
            for (int j = k >> 1; j > 0; j >>= 1) {
                __syncthreads();
                const int jm1 = j - 1;
#pragma unroll
                for (int q = 0; q < 2; q++) {
                    int p  = tid + 256 * q;               // pair 0..511
                    int i  = ((p & ~jm1) << 1) | (p & jm1);
                    int ix = i + j;
                    unsigned long long a = sg[i], bv = sg[ix];
                    bool desc = ((i & k) == 0);
                    if (desc ? (a < bv) : (a > bv)) { sg[i] = bv; sg[ix] = a; }
                }
            }
        }
        __syncthreads();

        if (tid < 32) {
            int kept = nms_scan(sg, MCAP, b, c, mb, tid);
            if (tid == 0) s_kept = kept;
        }
        __syncthreads();
        if (s_kept >= OUT_K || Tthr <= G) {       // batch sufficed (exact)
            if (tid == 0) g_ccnt[b][c] = s_kept;
            return;
        }
    }

    // ---- FALLBACK (rare): full 2048 sort + scan, exact ----
#pragma unroll 1
    for (int k = 2; k <= NN; k <<= 1) {
#pragma unroll 1
        for (int j = k >> 1; j > 0; j >>= 1) {
            __syncthreads();
            const int jm1 = j - 1;
#pragma unroll
            for (int q = 0; q < 4; q++) {
                int p  = tid + 256 * q;                   // pair 0..1023
                int i  = ((p & ~jm1) << 1) | (p & jm1);
                int ix = i + j;
                unsigned long long a = sk[i], bv = sk[ix];
                bool desc = ((i & k) == 0);
                if (desc ? (a < bv) : (a > bv)) { sk[i] = bv; sk[ix] = a; }
            }
        }
    }
    __syncthreads();
    if (tid < 32) {
        int kept = nms_scan(sk, NN, b, c, mb, tid);
        if (tid == 0) g_ccnt[b][c] = kept;
    }
}

// ---------------------------------------------------------------------------
// Kernel 3: per-batch top-200 via 3-level radix-select (24-bit prefix) +
//   512 bitonic. Level 3 uses register counters (high byte in {0x3C..0x3F}).
// ---------------------------------------------------------------------------
__global__ __launch_bounds__(256) void topk_kernel(const float* __restrict__ x,
                                                   float* __restrict__ out) {
    const int b = blockIdx.x;
    const int tid = threadIdx.x;
    __shared__ int s_cnt[CC];
    __shared__ int s_hist[256];
    __shared__ int s_scan[256];
    __shared__ unsigned long long s_key[512];
    __shared__ uint32_t s_pay[512];
    __shared__ int s_T, s_cut, s_num;

    if (tid == 0) s_T = 0;
    if (tid < CC) s_cnt[tid] = g_ccnt[b][tid];
    __syncthreads();
    if (tid < CC) atomicAdd(&s_T, s_cnt[tid]);
    __syncthreads();
    const int T = s_T;
    int k = (T < OUT_K) ? T : OUT_K;
    const int kinit = k;

    uint32_t S = 0;        // cutoff prefix, built MSB-byte down (3 levels)
    if (k > 0) {
#pragma unroll 1
        for (int lev = 3; lev >= 1; lev--) {
            s_hist[tid] = 0;
            __syncthreads();
            if (lev == 3) {
                int c0 = 0, c1 = 0, c2 = 0, c3 = 0;
                for (int idx = tid; idx < CC * OUT_K; idx += 256) {
                    int c = idx / OUT_K, slot = idx - c * OUT_K;
                    if (slot < s_cnt[c]) {
                        uint32_t d = ((uint32_t)(g_ckey[b][c][slot] >> 56)) - 0x3Cu;
                        c0 += (d == 0); c1 += (d == 1); c2 += (d == 2); c3 += (d == 3);
                    }
                }
                if (c0) atomicAdd(&s_hist[0x3C], c0);
                if (c1) atomicAdd(&s_hist[0x3D], c1);
                if (c2) atomicAdd(&s_hist[0x3E], c2);
                if (c3) atomicAdd(&s_hist[0x3F], c3);
            } else {
                for (int idx = tid; idx < CC * OUT_K; idx += 256) {
                    int c = idx / OUT_K, slot = idx - c * OUT_K;
                    if (slot < s_cnt[c]) {
                        uint32_t hi = (uint32_t)(g_ckey[b][c][slot] >> 32);
                        if ((hi >> ((lev + 1) * 8)) == (S >> ((lev + 1) * 8)))
                            atomicAdd(&s_hist[(hi >> (lev * 8)) & 255], 1);
                    }
                }
            }
            __syncthreads();
            int h = s_hist[tid];
            s_scan[tid] = h;
            __syncthreads();
#pragma unroll
            for (int off = 1; off < 256; off <<= 1) {
                int v2 = (tid + off < 256) ? s_scan[tid + off] : 0;
                __syncthreads();
                s_scan[tid] += v2;
                __syncthreads();
            }
            int cnt_gt = s_scan[tid] - h;
            if (cnt_gt < k && k <= cnt_gt + h) { s_cut = tid; s_num = cnt_gt; }
            __syncthreads();
            S |= ((uint32_t)s_cut) << (lev * 8);
            k -= s_num;
            __syncthreads();
        }
    }

    if (tid == 0) s_num = 0;
    __syncthreads();
    if (kinit > 0) {
        for (int idx = tid; idx < CC * OUT_K; idx += 256) {
            int c = idx / OUT_K, slot = idx - c * OUT_K;
            if (slot < s_cnt[c]) {
                unsigned long long key = g_ckey[b][c][slot];
                if ((uint32_t)(key >> 32) >= S) {
                    int p_ = atomicAdd(&s_num, 1);
                    if (p_ < 512) { s_key[p_] = key; s_pay[p_] = (uint32_t)idx; }
                }
            }
        }
    }
    __syncthreads();
    int num = s_num < 512 ? s_num : 512;
    for (int i2 = num + tid; i2 < 512; i2 += 256) { s_key[i2] = 0ull; s_pay[i2] = 0u; }
    __syncthreads();

#pragma unroll 1
    for (int kk = 2; kk <= 512; kk <<= 1) {
#pragma unroll 1
        for (int j = kk >> 1; j > 0; j >>= 1) {
            int i2 = ((tid & ~(j - 1)) << 1) | (tid & (j - 1));
            int ix = i2 + j;
            unsigned long long a = s_key[i2], bb2 = s_key[ix];
            bool desc2 = ((i2 & kk) == 0);
            if (desc2 ? (a < bb2) : (a > bb2)) {
                s_key[i2] = bb2; s_key[ix] = a;
                uint32_t tp = s_pay[i2]; s_pay[i2] = s_pay[ix]; s_pay[ix] = tp;
            }
            __syncthreads();
        }
    }

    if (tid < OUT_K) {
        float* o = out + ((size_t)b * OUT_K + tid) * 6;
        if (tid < kinit) {
            unsigned long long key = s_key[tid];
            uint32_t pay = s_pay[tid];
            int c = pay / OUT_K, slot = pay - c * OUT_K;
            int bi = g_cbox[b][c][slot];
            const float* bx = x + ((size_t)b * NN + bi) * ROWF;
            o[0] = (float)c;
            o[1] = __uint_as_float((uint32_t)(key >> 32));
            o[2] = fminf(fmaxf(bx[0], 0.f), 1.f);
            o[3] = fminf(fmaxf(bx[1], 0.f), 1.f);
            o[4] = fminf(fmaxf(bx[2], 0.f), 1.f);
            o[5] = fminf(fmaxf(bx[3], 0.f), 1.f);
        } else {
            o[0] = o[1] = o[2] = o[3] = o[4] = o[5] = 0.f;
        }
    }
}

extern "C" void kernel_launch(void* const* d_in, const int* in_sizes, int n_in,
                              void* d_out, int out_size) {
    const float* x = (const float*)d_in[0];
    float* out = (float*)d_out;
    (void)in_sizes; (void)n_in; (void)out_size;

    dim3 g1(NN / 16, BB);
    iou_mask_kernel<<<g1, 256>>>(x);
    dim3 g2(CC, BB);
    nms_kernel<<<g2, 256>>>(x);
    topk_kernel<<<BB, 256>>>(x, out);
}

// round 14
// speedup vs baseline: 1.5962x; 1.0876x over previous
#include <cuda_runtime.h>
#include <stdint.h>

#define BB 8
#define NN 2048
#define CC 80
#define ROWF 84          // floats per box row: 4 box + 80 scores
#define NW 64            // uint32 words per mask row (2048/32)
#define OUT_K 200
#define SCORE_THR 0.01f
#define FULLM 0xFFFFFFFFu
#define MSEL 448         // selection rank for the NMS batch
#define MCAP 512         // batch capacity (power of two, sorted size)

// Persistent scratch (no allocations allowed)
__device__ uint32_t           g_mask[BB][NN][NW];          // 4 MB  : IoU>0.5 bitmask
__device__ float              g_st[BB][CC][NN];            // 5.2MB: transposed scores
__device__ unsigned long long g_fb[BB][CC][NN];            // 10 MB: fallback sort scratch
__device__ unsigned long long g_ckey[BB][CC][OUT_K];       // (score_bits<<32)|~flatidx
__device__ int                g_cbox[BB][CC][OUT_K];       // original box index
__device__ int                g_ccnt[BB][CC];

// ---------------------------------------------------------------------------
// Kernel 0: transpose scores x[b][n][4+c] -> g_st[b][c][n]. grid(NN/32, B).
// ---------------------------------------------------------------------------
__global__ __launch_bounds__(256) void transpose_kernel(const float* __restrict__ x) {
    const int b  = blockIdx.y;
    const int n0 = blockIdx.x * 32;
    __shared__ float st[32][85];                 // 85: odd stride, conflict-free
    const float* src = x + ((size_t)b * NN + n0) * ROWF;
    for (int idx = threadIdx.x; idx < 32 * ROWF; idx += 256) {
        int rr = idx / ROWF, cc = idx - rr * ROWF;
        st[rr][cc] = src[idx];                   // fully coalesced (contiguous)
    }
    __syncthreads();
    for (int idx = threadIdx.x; idx < CC * 32; idx += 256) {
        int c = idx >> 5, n = idx & 31;
        g_st[b][c][n0 + n] = st[n][4 + c];       // coalesced 128B per warp
    }
}

// ---------------------------------------------------------------------------
// Kernel 1: IoU>0.5 bitmask. grid(NN/16, B), 256 threads. (stable, 46us)
// ---------------------------------------------------------------------------
__global__ __launch_bounds__(256) void iou_mask_kernel(const float* __restrict__ x) {
    const int b = blockIdx.y;
    const int r = threadIdx.x >> 6;        // 0..3
    const int w = threadIdx.x & 63;        // 0..63
    const int i0 = blockIdx.x * 16 + r * 4;

    __shared__ float4 sb[NN];              // 32 KB (xor-swizzled)
    __shared__ float  sa[NN];              // 8 KB

    const float* xb = x + (size_t)b * NN * ROWF;
    for (int j = threadIdx.x; j < NN; j += 256) {
        float4 v = *reinterpret_cast<const float4*>(xb + (size_t)j * ROWF);
        int pj = j ^ ((j >> 5) & 31);
        sb[pj] = v;
        sa[pj] = __fmul_rn(v.z - v.x, v.w - v.y);
    }
    __syncthreads();

    float4 bi[4]; float ai[4];
#pragma unroll
    for (int q = 0; q < 4; q++) {
        int pi = (i0 + q) ^ (((i0 + q) >> 5) & 31);
        bi[q] = sb[pi];
        ai[q] = sa[pi];
    }

    uint32_t word[4] = {0, 0, 0, 0};
    const int j0 = w * 32;
    const int m  = w & 31;
#pragma unroll 8
    for (int t = 0; t < 32; t++) {
        int pj = j0 + (t ^ m);             // swizzled: conflict-free
        float4 bj = sb[pj];
        float  aj = sa[pj];
#pragma unroll
        for (int q = 0; q < 4; q++) {
            float lx = fmaxf(bi[q].x, bj.x), ly = fmaxf(bi[q].y, bj.y);
            float rx = fminf(bi[q].z, bj.z), ry = fminf(bi[q].w, bj.w);
            float ww = fmaxf(__fadd_rn(rx, -lx), 0.f);
            float hh = fmaxf(__fadd_rn(ry, -ly), 0.f);
            float inter = __fmul_rn(ww, hh);
            float uni   = __fadd_rn(__fadd_rn(ai[q], aj), -inter);
            float lhs   = __fadd_rn(inter, inter);          // exact
            bool bit = lhs > uni;                            // == (inter/uni > 0.5)
            if (fabsf(__fadd_rn(lhs, -uni)) <= __fmul_rn(1e-6f, uni)) {
                bit = __fdiv_rn(inter, fmaxf(uni, 1e-8f)) > 0.5f;   // boundary: exact
            }
            if (bit) word[q] |= 1u << t;
        }
    }
#pragma unroll
    for (int q = 0; q < 4; q++) g_mask[b][i0 + q][w] = word[q];
}

// ---------------------------------------------------------------------------
// Warp-0 chunked greedy NMS over a descending-sorted key array.
// ---------------------------------------------------------------------------
__device__ __forceinline__ int nms_scan(const unsigned long long* __restrict__ arr,
                                        int len, int b, int c,
                                        const uint32_t* __restrict__ mb, int lane) {
    uint32_t a0 = FULLM, a1 = FULLM;     // alive mask over ORIGINAL indices
    int kept = 0;
    int p = 0;
    while (p < len && kept < OUT_K) {
        const int pp = p + lane;
        unsigned long long key = arr[pp];
        float s = __uint_as_float((uint32_t)(key >> 32));
        bool sok = (s > SCORE_THR);
        int oi  = (int)(FULLM - (uint32_t)(key & FULLM));
        int wrd = (oi >> 5) & 63;
        uint32_t v0 = __shfl_sync(FULLM, a0, wrd >> 1);
        uint32_t v1 = __shfl_sync(FULLM, a1, wrd >> 1);
        uint32_t av = (wrd & 1) ? v1 : v0;
        bool alive = (av >> (oi & 31)) & 1u;

        uint32_t bal_s = __ballot_sync(FULLM, sok);
        uint32_t cand  = __ballot_sync(FULLM, sok && alive);

        if (cand) {
            uint32_t sup = 0;
            if (sok && alive) {
                uint32_t mm = cand & ((1u << lane) - 1u);
                while (mm) {
                    int i = __ffs(mm) - 1; mm &= mm - 1;
                    int oii = (int)(FULLM - (uint32_t)(arr[p + i] & FULLM));
                    uint32_t wv = __ldg(mb + (size_t)oii * NW + (oi >> 5));
                    sup |= ((wv >> (oi & 31)) & 1u) << i;
                }
            }
            uint32_t keptm = 0, rem = cand;
            const int room = OUT_K - kept;
            while (rem && (int)__popc(keptm) < room) {
                int i = __ffs(rem) - 1;
                keptm |= 1u << i;
                rem   &= ~(1u << i);
                uint32_t supby = __ballot_sync(FULLM, (sup >> i) & 1u);
                rem &= ~supby;
            }
            if ((keptm >> lane) & 1u) {
                int slot = kept + __popc(keptm & ((1u << lane) - 1u));
                uint32_t flat = (uint32_t)(c * NN + pp);
                g_ckey[b][c][slot] = (key & 0xFFFFFFFF00000000ull)
                                   | (unsigned long long)(FULLM - flat);
                g_cbox[b][c][slot] = oi;
            }
            uint32_t am = keptm;
            while (am) {
                int i = __ffs(am) - 1; am &= am - 1;
                int oii = (int)(FULLM - (uint32_t)(arr[p + i] & FULLM));
                const uint32_t* __restrict__ row = mb + (size_t)oii * NW;
                a0 &= ~row[2 * lane];
                a1 &= ~row[2 * lane + 1];
            }
            kept += __popc(keptm);
        }
        if (bal_s != FULLM) break;          // sorted: everything later fails score
        p += 32;
    }
    return kept;
}

// ---------------------------------------------------------------------------
// Kernel 2: one block (256 thr) per (class, batch).
//   Single coalesced sweep (scores kept in registers) -> exact top-MSEL
//   selection (2-level byte radix) -> 512 bitonic -> chunked NMS.
//   Exact fallback: full sort of all >thr keys in global scratch.
// ---------------------------------------------------------------------------
__global__ __launch_bounds__(256) void nms_kernel() {
    const int b = blockIdx.y, c = blockIdx.x;
    __shared__ unsigned long long sg[MCAP];     // 4 KB: selected batch
    __shared__ int s_hist[256];
    __shared__ int s_scan[256];
    __shared__ int s_Tthr, s_num, s_cut, s_rem, s_kept;

    const int tid = threadIdx.x;
    const float* sc = g_st[b][c];
    const uint32_t* mb = &g_mask[b][0][0];
    const uint32_t THR_BITS = __float_as_uint(SCORE_THR);

    if (tid == 0) { s_Tthr = 0; s_num = 0; }
    s_hist[tid] = 0;
    __syncthreads();

    // ---- single coalesced load: 8 scores/thread stay in registers ----
    uint32_t sbits[8];
    {
        float4 v0 = *reinterpret_cast<const float4*>(sc + tid * 8);
        float4 v1 = *reinterpret_cast<const float4*>(sc + tid * 8 + 4);
        sbits[0] = __float_as_uint(v0.x); sbits[1] = __float_as_uint(v0.y);
        sbits[2] = __float_as_uint(v0.z); sbits[3] = __float_as_uint(v0.w);
        sbits[4] = __float_as_uint(v1.x); sbits[5] = __float_as_uint(v1.y);
        sbits[6] = __float_as_uint(v1.z); sbits[7] = __float_as_uint(v1.w);
    }

    // ---- level-1 histogram (top byte), hot bins in registers ----
    {
        int mythr = 0, cF = 0, cE = 0, cD = 0;
#pragma unroll
        for (int t = 0; t < 8; t++) {
            mythr += (sbits[t] > THR_BITS);
            uint32_t hb = sbits[t] >> 24;
            if      (hb == 0x3F) cF++;
            else if (hb == 0x3E) cE++;
            else if (hb == 0x3D) cD++;
            else atomicAdd(&s_hist[hb], 1);
        }
        if (cF) atomicAdd(&s_hist[0x3F], cF);
        if (cE) atomicAdd(&s_hist[0x3E], cE);
        if (cD) atomicAdd(&s_hist[0x3D], cD);
        if (mythr) atomicAdd(&s_Tthr, mythr);
    }
    __syncthreads();

    // ---- suffix scan level 1: bin containing rank MSEL ----
    int h = s_hist[tid];
    s_scan[tid] = h;
    __syncthreads();
#pragma unroll
    for (int off = 1; off < 256; off <<= 1) {
        int v2 = (tid + off < 256) ? s_scan[tid + off] : 0;
        __syncthreads();
        s_scan[tid] += v2;
        __syncthreads();
    }
    {
        int cnt_gt = s_scan[tid] - h;
        if (cnt_gt < MSEL && MSEL <= cnt_gt + h) { s_cut = tid; s_rem = MSEL - cnt_gt; }
    }
    __syncthreads();
    const uint32_t b3 = (uint32_t)s_cut;
    const int k2 = s_rem;
    s_hist[tid] = 0;
    __syncthreads();

    // ---- level-2 histogram (byte2) within byte3 == b3 (registers, no loads) ----
#pragma unroll
    for (int t = 0; t < 8; t++)
        if ((sbits[t] >> 24) == b3)
            atomicAdd(&s_hist[(sbits[t] >> 16) & 255], 1);
    __syncthreads();
    h = s_hist[tid];
    s_scan[tid] = h;
    __syncthreads();
#pragma unroll
    for (int off = 1; off < 256; off <<= 1) {
        int v2 = (tid + off < 256) ? s_scan[tid + off] : 0;
        __syncthreads();
        s_scan[tid] += v2;
        __syncthreads();
    }
    {
        int cnt_gt = s_scan[tid] - h;
        if (cnt_gt < k2 && k2 <= cnt_gt + h) s_cut = tid;
    }
    __syncthreads();
    const uint32_t S16 = (b3 << 8) | (uint32_t)s_cut;   // 16-bit cutoff prefix

    // ---- gather batch: prefix >= S16 AND score > THR (registers) ----
#pragma unroll
    for (int t = 0; t < 8; t++) {
        if ((sbits[t] >> 16) >= S16 && sbits[t] > THR_BITS) {
            int p_ = atomicAdd(&s_num, 1);
            if (p_ < MCAP)
                sg[p_] = ((unsigned long long)sbits[t] << 32)
                       | (unsigned long long)(FULLM - (uint32_t)(tid * 8 + t));
        }
    }
    __syncthreads();
    const int G = s_num;
    const int Tthr = s_Tthr;

    if (G <= MCAP) {
        for (int i = G + tid; i < MCAP; i += 256) sg[i] = 0ull;   // pad

        // ---- bitonic sort MCAP=512 descending: 1 pair per thread ----
#pragma unroll 1
        for (int k = 2; k <= MCAP; k <<= 1) {
#pragma unroll 1
            for (int j = k >> 1; j > 0; j >>= 1) {
                __syncthreads();
                const int jm1 = j - 1;
                int i  = ((tid & ~jm1) << 1) | (tid & jm1);
                int ix = i + j;
                unsigned long long a = sg[i], bv = sg[ix];
                bool desc = ((i & k) == 0);
                if (desc ? (a < bv) : (a > bv)) { sg[i] = bv; sg[ix] = a; }
            }
        }
        __syncthreads();

        if (tid < 32) {
            int kept = nms_scan(sg, MCAP, b, c, mb, tid);
            if (tid == 0) s_kept = kept;
        }
        __syncthreads();
        if (s_kept >= OUT_K || Tthr <= G) {       // batch sufficed (exact)
            if (tid == 0) g_ccnt[b][c] = s_kept;
            return;
        }
    }

    // ---- FALLBACK (rare, exact): sort ALL >thr keys in global scratch ----
    if (tid == 0) s_num = 0;
    __syncthreads();
    unsigned long long* fb = &g_fb[b][c][0];
#pragma unroll
    for (int t = 0; t < 8; t++) {
        if (sbits[t] > THR_BITS) {
            int p_ = atomicAdd(&s_num, 1);
            fb[p_] = ((unsigned long long)sbits[t] << 32)
                   | (unsigned long long)(FULLM - (uint32_t)(tid * 8 + t));
        }
    }
    __syncthreads();
    for (int i = s_num + tid; i < NN; i += 256) fb[i] = 0ull;
#pragma unroll 1
    for (int k = 2; k <= NN; k <<= 1) {
#pragma unroll 1
        for (int j = k >> 1; j > 0; j >>= 1) {
            __syncthreads();
            const int jm1 = j - 1;
#pragma unroll
            for (int q = 0; q < 4; q++) {
                int p_  = tid + 256 * q;
                int i   = ((p_ & ~jm1) << 1) | (p_ & jm1);
                int ix  = i + j;
                unsigned long long a = fb[i], bv = fb[ix];
                bool desc = ((i & k) == 0);
                if (desc ? (a < bv) : (a > bv)) { fb[i] = bv; fb[ix] = a; }
            }
        }
    }
    __syncthreads();
    if (tid < 32) {
        int kept = nms_scan(fb, NN, b, c, mb, tid);
        if (tid == 0) g_ccnt[b][c] = kept;
    }
}

// ---------------------------------------------------------------------------
// Kernel 3: per-batch top-200 via 3-level radix-select (24-bit prefix) +
//   512 bitonic. Level 3 uses register counters (high byte in {0x3C..0x3F}).
// ---------------------------------------------------------------------------
__global__ __launch_bounds__(256) void topk_kernel(const float* __restrict__ x,
                                                   float* __restrict__ out) {
    const int b = blockIdx.x;
    const int tid = threadIdx.x;
    __shared__ int s_cnt[CC];
    __shared__ int s_hist[256];
    __shared__ int s_scan[256];
    __shared__ unsigned long long s_key[512];
    __shared__ uint32_t s_pay[512];
    __shared__ int s_T, s_cut, s_num;

    if (tid == 0) s_T = 0;
    if (tid < CC) s_cnt[tid] = g_ccnt[b][tid];
    __syncthreads();
    if (tid < CC) atomicAdd(&s_T, s_cnt[tid]);
    __syncthreads();
    const int T = s_T;
    int k = (T < OUT_K) ? T : OUT_K;
    const int kinit = k;

    uint32_t S = 0;        // cutoff prefix, built MSB-byte down (3 levels)
    if (k > 0) {
#pragma unroll 1
        for (int lev = 3; lev >= 1; lev--) {
            s_hist[tid] = 0;
            __syncthreads();
            if (lev == 3) {
                int c0 = 0, c1 = 0, c2 = 0, c3 = 0;
                for (int idx = tid; idx < CC * OUT_K; idx += 256) {
                    int c = idx / OUT_K, slot = idx - c * OUT_K;
                    if (slot < s_cnt[c]) {
                        uint32_t d = ((uint32_t)(g_ckey[b][c][slot] >> 56)) - 0x3Cu;
                        c0 += (d == 0); c1 += (d == 1); c2 += (d == 2); c3 += (d == 3);
                    }
                }
                if (c0) atomicAdd(&s_hist[0x3C], c0);
                if (c1) atomicAdd(&s_hist[0x3D], c1);
                if (c2) atomicAdd(&s_hist[0x3E], c2);
                if (c3) atomicAdd(&s_hist[0x3F], c3);
            } else {
                for (int idx = tid; idx < CC * OUT_K; idx += 256) {
                    int c = idx / OUT_K, slot = idx - c * OUT_K;
                    if (slot < s_cnt[c]) {
                        uint32_t hi = (uint32_t)(g_ckey[b][c][slot] >> 32);
                        if ((hi >> ((lev + 1) * 8)) == (S >> ((lev + 1) * 8)))
                            atomicAdd(&s_hist[(hi >> (lev * 8)) & 255], 1);
                    }
                }
            }
            __syncthreads();
            int h = s_hist[tid];
            s_scan[tid] = h;
            __syncthreads();
#pragma unroll
            for (int off = 1; off < 256; off <<= 1) {
                int v2 = (tid + off < 256) ? s_scan[tid + off] : 0;
                __syncthreads();
                s_scan[tid] += v2;
                __syncthreads();
            }
            int cnt_gt = s_scan[tid] - h;
            if (cnt_gt < k && k <= cnt_gt + h) { s_cut = tid; s_num = cnt_gt; }
            __syncthreads();
            S |= ((uint32_t)s_cut) << (lev * 8);
            k -= s_num;
            __syncthreads();
        }
    }

    if (tid == 0) s_num = 0;
    __syncthreads();
    if (kinit > 0) {
        for (int idx = tid; idx < CC * OUT_K; idx += 256) {
            int c = idx / OUT_K, slot = idx - c * OUT_K;
            if (slot < s_cnt[c]) {
                unsigned long long key = g_ckey[b][c][slot];
                if ((uint32_t)(key >> 32) >= S) {
                    int p_ = atomicAdd(&s_num, 1);
                    if (p_ < 512) { s_key[p_] = key; s_pay[p_] = (uint32_t)idx; }
                }
            }
        }
    }
    __syncthreads();
    int num = s_num < 512 ? s_num : 512;
    for (int i2 = num + tid; i2 < 512; i2 += 256) { s_key[i2] = 0ull; s_pay[i2] = 0u; }
    __syncthreads();

#pragma unroll 1
    for (int kk = 2; kk <= 512; kk <<= 1) {
#pragma unroll 1
        for (int j = kk >> 1; j > 0; j >>= 1) {
            int i2 = ((tid & ~(j - 1)) << 1) | (tid & (j - 1));
            int ix = i2 + j;
            unsigned long long a = s_key[i2], bb2 = s_key[ix];
            bool desc2 = ((i2 & kk) == 0);
            if (desc2 ? (a < bb2) : (a > bb2)) {
                s_key[i2] = bb2; s_key[ix] = a;
                uint32_t tp = s_pay[i2]; s_pay[i2] = s_pay[ix]; s_pay[ix] = tp;
            }
            __syncthreads();
        }
    }

    if (tid < OUT_K) {
        float* o = out + ((size_t)b * OUT_K + tid) * 6;
        if (tid < kinit) {
            unsigned long long key = s_key[tid];
            uint32_t pay = s_pay[tid];
            int c = pay / OUT_K, slot = pay - c * OUT_K;
            int bi = g_cbox[b][c][slot];
            const float* bx = x + ((size_t)b * NN + bi) * ROWF;
            o[0] = (float)c;
            o[1] = __uint_as_float((uint32_t)(key >> 32));
            o[2] = fminf(fmaxf(bx[0], 0.f), 1.f);
            o[3] = fminf(fmaxf(bx[1], 0.f), 1.f);
            o[4] = fminf(fmaxf(bx[2], 0.f), 1.f);
            o[5] = fminf(fmaxf(bx[3], 0.f), 1.f);
        } else {
            o[0] = o[1] = o[2] = o[3] = o[4] = o[5] = 0.f;
        }
    }
}

extern "C" void kernel_launch(void* const* d_in, const int* in_sizes, int n_in,
                              void* d_out, int out_size) {
    const float* x = (const float*)d_in[0];
    float* out = (float*)d_out;
    (void)in_sizes; (void)n_in; (void)out_size;

    dim3 g0(NN / 32, BB);
    transpose_kernel<<<g0, 256>>>(x);
    dim3 g1(NN / 16, BB);
    iou_mask_kernel<<<g1, 256>>>(x);
    dim3 g2(CC, BB);
    nms_kernel<<<g2, 256>>>();
    topk_kernel<<<BB, 256>>>(x, out);
}

// round 15
// speedup vs baseline: 1.9442x; 1.2180x over previous
#include <cuda_runtime.h>
#include <stdint.h>

#define BB 8
#define NN 2048
#define CC 80
#define ROWF 84          // floats per box row: 4 box + 80 scores
#define NW 64            // uint32 words per mask row (2048/32)
#define OUT_K 200
#define SCORE_THR 0.01f
#define FULLM 0xFFFFFFFFu
#define MSEL 448         // selection rank for the NMS batch
#define MCAP 512         // batch capacity (power of two, sorted size)

// Persistent scratch (no allocations allowed)
__device__ uint32_t           g_mask[BB][NN][NW];          // 4 MB  : IoU>0.5 bitmask
__device__ float              g_st[BB][CC][NN];            // 5.2MB: transposed scores
__device__ unsigned long long g_fb[BB][CC][NN];            // 10 MB: fallback sort scratch
__device__ unsigned long long g_ckey[BB][CC][OUT_K];       // (score_bits<<32)|~flatidx
__device__ int                g_cbox[BB][CC][OUT_K];       // original box index
__device__ int                g_ccnt[BB][CC];

// ---------------------------------------------------------------------------
// Warp-0 suffix scan over a 256-bin histogram: finds bin `cut` such that
// count(> cut-bin) < k <= count(>= cut-bin); rem = k - count(>bin).
// Caller must __syncthreads() before (hist ready) and after (cut published).
// ---------------------------------------------------------------------------
__device__ __forceinline__ void warp_suffix_cut(const int* __restrict__ hist, int k,
                                                int tid, int* out_cut, int* out_rem) {
    if (tid < 32) {
        int h[8], suf[8]; int run = 0;
#pragma unroll
        for (int t = 7; t >= 0; t--) { h[t] = hist[tid * 8 + t]; run += h[t]; suf[t] = run; }
        int s = run;
#pragma unroll
        for (int off = 1; off < 32; off <<= 1) {
            int v = __shfl_down_sync(FULLM, s, off);
            if (tid + off < 32) s += v;
        }
        int excl = s - run;                  // sum over lanes > tid
#pragma unroll
        for (int t = 0; t < 8; t++) {
            int sfx = excl + suf[t];         // count >= bin(8*tid+t)
            int cnt_gt = sfx - h[t];
            if (cnt_gt < k && k <= sfx) { *out_cut = tid * 8 + t; *out_rem = k - cnt_gt; }
        }
    }
}

// ---------------------------------------------------------------------------
// Kernel 0: transpose scores x[b][n][4+c] -> g_st[b][c][n]. grid(NN/32, B).
// ---------------------------------------------------------------------------
__global__ __launch_bounds__(256) void transpose_kernel(const float* __restrict__ x) {
    const int b  = blockIdx.y;
    const int n0 = blockIdx.x * 32;
    __shared__ float st[32][85];                 // 85: odd stride, conflict-free
    const float* src = x + ((size_t)b * NN + n0) * ROWF;
    for (int idx = threadIdx.x; idx < 32 * ROWF; idx += 256) {
        int rr = idx / ROWF, cc = idx - rr * ROWF;
        st[rr][cc] = src[idx];                   // fully coalesced (contiguous)
    }
    __syncthreads();
    for (int idx = threadIdx.x; idx < CC * 32; idx += 256) {
        int c = idx >> 5, n = idx & 31;
        g_st[b][c][n0 + n] = st[n][4 + c];       // coalesced 128B per warp
    }
}

// ---------------------------------------------------------------------------
// Kernel 1: IoU>0.5 bitmask. grid(NN/16, B), 256 threads. (stable, 46us)
// ---------------------------------------------------------------------------
__global__ __launch_bounds__(256) void iou_mask_kernel(const float* __restrict__ x) {
    const int b = blockIdx.y;
    const int r = threadIdx.x >> 6;        // 0..3
    const int w = threadIdx.x & 63;        // 0..63
    const int i0 = blockIdx.x * 16 + r * 4;

    __shared__ float4 sb[NN];              // 32 KB (xor-swizzled)
    __shared__ float  sa[NN];              // 8 KB

    const float* xb = x + (size_t)b * NN * ROWF;
    for (int j = threadIdx.x; j < NN; j += 256) {
        float4 v = *reinterpret_cast<const float4*>(xb + (size_t)j * ROWF);
        int pj = j ^ ((j >> 5) & 31);
        sb[pj] = v;
        sa[pj] = __fmul_rn(v.z - v.x, v.w - v.y);
    }
    __syncthreads();

    float4 bi[4]; float ai[4];
#pragma unroll
    for (int q = 0; q < 4; q++) {
        int pi = (i0 + q) ^ (((i0 + q) >> 5) & 31);
        bi[q] = sb[pi];
        ai[q] = sa[pi];
    }

    uint32_t word[4] = {0, 0, 0, 0};
    const int j0 = w * 32;
    const int m  = w & 31;
#pragma unroll 8
    for (int t = 0; t < 32; t++) {
        int pj = j0 + (t ^ m);             // swizzled: conflict-free
        float4 bj = sb[pj];
        float  aj = sa[pj];
#pragma unroll
        for (int q = 0; q < 4; q++) {
            float lx = fmaxf(bi[q].x, bj.x), ly = fmaxf(bi[q].y, bj.y);
            float rx = fminf(bi[q].z, bj.z), ry = fminf(bi[q].w, bj.w);
            float ww = fmaxf(__fadd_rn(rx, -lx), 0.f);
            float hh = fmaxf(__fadd_rn(ry, -ly), 0.f);
            float inter = __fmul_rn(ww, hh);
            float uni   = __fadd_rn(__fadd_rn(ai[q], aj), -inter);
            float lhs   = __fadd_rn(inter, inter);          // exact
            bool bit = lhs > uni;                            // == (inter/uni > 0.5)
            if (fabsf(__fadd_rn(lhs, -uni)) <= __fmul_rn(1e-6f, uni)) {
                bit = __fdiv_rn(inter, fmaxf(uni, 1e-8f)) > 0.5f;   // boundary: exact
            }
            if (bit) word[q] |= 1u << t;
        }
    }
#pragma unroll
    for (int q = 0; q < 4; q++) g_mask[b][i0 + q][w] = word[q];
}

// ---------------------------------------------------------------------------
// Warp-0 chunked greedy NMS over a descending-sorted key array.
// ---------------------------------------------------------------------------
__device__ __forceinline__ int nms_scan(const unsigned long long* __restrict__ arr,
                                        int len, int b, int c,
                                        const uint32_t* __restrict__ mb, int lane) {
    uint32_t a0 = FULLM, a1 = FULLM;     // alive mask over ORIGINAL indices
    int kept = 0;
    int p = 0;
    while (p < len && kept < OUT_K) {
        const int pp = p + lane;
        unsigned long long key = arr[pp];
        float s = __uint_as_float((uint32_t)(key >> 32));
        bool sok = (s > SCORE_THR);
        int oi  = (int)(FULLM - (uint32_t)(key & FULLM));
        int wrd = (oi >> 5) & 63;
        uint32_t v0 = __shfl_sync(FULLM, a0, wrd >> 1);
        uint32_t v1 = __shfl_sync(FULLM, a1, wrd >> 1);
        uint32_t av = (wrd & 1) ? v1 : v0;
        bool alive = (av >> (oi & 31)) & 1u;

        uint32_t bal_s = __ballot_sync(FULLM, sok);
        uint32_t cand  = __ballot_sync(FULLM, sok && alive);

        if (cand) {
            uint32_t sup = 0;
            if (sok && alive) {
                uint32_t mm = cand & ((1u << lane) - 1u);
                while (mm) {
                    int i = __ffs(mm) - 1; mm &= mm - 1;
                    int oii = (int)(FULLM - (uint32_t)(arr[p + i] & FULLM));
                    uint32_t wv = __ldg(mb + (size_t)oii * NW + (oi >> 5));
                    sup |= ((wv >> (oi & 31)) & 1u) << i;
                }
            }
            uint32_t keptm = 0, rem = cand;
            const int room = OUT_K - kept;
            while (rem && (int)__popc(keptm) < room) {
                int i = __ffs(rem) - 1;
                keptm |= 1u << i;
                rem   &= ~(1u << i);
                uint32_t supby = __ballot_sync(FULLM, (sup >> i) & 1u);
                rem &= ~supby;
            }
            if ((keptm >> lane) & 1u) {
                int slot = kept + __popc(keptm & ((1u << lane) - 1u));
                uint32_t flat = (uint32_t)(c * NN + pp);
                g_ckey[b][c][slot] = (key & 0xFFFFFFFF00000000ull)
                                   | (unsigned long long)(FULLM - flat);
                g_cbox[b][c][slot] = oi;
            }
            uint32_t am = keptm;
            while (am) {
                int i = __ffs(am) - 1; am &= am - 1;
                int oii = (int)(FULLM - (uint32_t)(arr[p + i] & FULLM));
                const uint32_t* __restrict__ row = mb + (size_t)oii * NW;
                a0 &= ~row[2 * lane];
                a1 &= ~row[2 * lane + 1];
            }
            kept += __popc(keptm);
        }
        if (bal_s != FULLM) break;          // sorted: everything later fails score
        p += 32;
    }
    return kept;
}

// ---------------------------------------------------------------------------
// Kernel 2: one block (256 thr) per (class, batch).
//   Single coalesced sweep (scores in registers) -> exact top-MSEL selection
//   (2-level byte radix, warp-scan cutoff) -> 512 bitonic -> chunked NMS.
//   Exact fallback: full sort of all >thr keys in global scratch.
// ---------------------------------------------------------------------------
__global__ __launch_bounds__(256) void nms_kernel() {
    const int b = blockIdx.y, c = blockIdx.x;
    __shared__ unsigned long long sg[MCAP];     // 4 KB: selected batch
    __shared__ int s_hist[256];
    __shared__ int s_Tthr, s_num, s_cut, s_rem, s_kept;

    const int tid = threadIdx.x;
    const float* sc = g_st[b][c];
    const uint32_t* mb = &g_mask[b][0][0];
    const uint32_t THR_BITS = __float_as_uint(SCORE_THR);

    if (tid == 0) { s_Tthr = 0; s_num = 0; }
    s_hist[tid] = 0;
    __syncthreads();

    // ---- single coalesced load: 8 scores/thread stay in registers ----
    uint32_t sbits[8];
    {
        float4 v0 = *reinterpret_cast<const float4*>(sc + tid * 8);
        float4 v1 = *reinterpret_cast<const float4*>(sc + tid * 8 + 4);
        sbits[0] = __float_as_uint(v0.x); sbits[1] = __float_as_uint(v0.y);
        sbits[2] = __float_as_uint(v0.z); sbits[3] = __float_as_uint(v0.w);
        sbits[4] = __float_as_uint(v1.x); sbits[5] = __float_as_uint(v1.y);
        sbits[6] = __float_as_uint(v1.z); sbits[7] = __float_as_uint(v1.w);
    }

    // ---- level-1 histogram (top byte), hot bins in registers ----
    {
        int mythr = 0, cF = 0, cE = 0, cD = 0;
#pragma unroll
        for (int t = 0; t < 8; t++) {
            mythr += (sbits[t] > THR_BITS);
            uint32_t hb = sbits[t] >> 24;
            if      (hb == 0x3F) cF++;
            else if (hb == 0x3E) cE++;
            else if (hb == 0x3D) cD++;
            else atomicAdd(&s_hist[hb], 1);
        }
        if (cF) atomicAdd(&s_hist[0x3F], cF);
        if (cE) atomicAdd(&s_hist[0x3E], cE);
        if (cD) atomicAdd(&s_hist[0x3D], cD);
        if (mythr) atomicAdd(&s_Tthr, mythr);
    }
    __syncthreads();
    warp_suffix_cut(s_hist, MSEL, tid, &s_cut, &s_rem);
    __syncthreads();
    const uint32_t b3 = (uint32_t)s_cut;
    const int k2 = s_rem;
    s_hist[tid] = 0;
    __syncthreads();

    // ---- level-2 histogram (byte2) within byte3 == b3 (registers) ----
#pragma unroll
    for (int t = 0; t < 8; t++)
        if ((sbits[t] >> 24) == b3)
            atomicAdd(&s_hist[(sbits[t] >> 16) & 255], 1);
    __syncthreads();
    warp_suffix_cut(s_hist, k2, tid, &s_cut, &s_rem);
    __syncthreads();
    const uint32_t S16 = (b3 << 8) | (uint32_t)s_cut;   // 16-bit cutoff prefix

    // ---- gather batch: prefix >= S16 AND score > THR (registers) ----
#pragma unroll
    for (int t = 0; t < 8; t++) {
        if ((sbits[t] >> 16) >= S16 && sbits[t] > THR_BITS) {
            int p_ = atomicAdd(&s_num, 1);
            if (p_ < MCAP)
                sg[p_] = ((unsigned long long)sbits[t] << 32)
                       | (unsigned long long)(FULLM - (uint32_t)(tid * 8 + t));
        }
    }
    __syncthreads();
    const int G = s_num;
    const int Tthr = s_Tthr;

    if (G <= MCAP) {
        for (int i = G + tid; i < MCAP; i += 256) sg[i] = 0ull;   // pad

        // ---- bitonic sort MCAP=512 descending: 1 pair per thread ----
#pragma unroll 1
        for (int k = 2; k <= MCAP; k <<= 1) {
#pragma unroll 1
            for (int j = k >> 1; j > 0; j >>= 1) {
                __syncthreads();
                const int jm1 = j - 1;
                int i  = ((tid & ~jm1) << 1) | (tid & jm1);
                int ix = i + j;
                unsigned long long a = sg[i], bv = sg[ix];
                bool desc = ((i & k) == 0);
                if (desc ? (a < bv) : (a > bv)) { sg[i] = bv; sg[ix] = a; }
            }
        }
        __syncthreads();

        if (tid < 32) {
            int kept = nms_scan(sg, MCAP, b, c, mb, tid);
            if (tid == 0) s_kept = kept;
        }
        __syncthreads();
        if (s_kept >= OUT_K || Tthr <= G) {       // batch sufficed (exact)
            if (tid == 0) g_ccnt[b][c] = s_kept;
            return;
        }
    }

    // ---- FALLBACK (rare, exact): sort ALL >thr keys in global scratch ----
    if (tid == 0) s_num = 0;
    __syncthreads();
    unsigned long long* fb = &g_fb[b][c][0];
#pragma unroll
    for (int t = 0; t < 8; t++) {
        if (sbits[t] > THR_BITS) {
            int p_ = atomicAdd(&s_num, 1);
            fb[p_] = ((unsigned long long)sbits[t] << 32)
                   | (unsigned long long)(FULLM - (uint32_t)(tid * 8 + t));
        }
    }
    __syncthreads();
    for (int i = s_num + tid; i < NN; i += 256) fb[i] = 0ull;
#pragma unroll 1
    for (int k = 2; k <= NN; k <<= 1) {
#pragma unroll 1
        for (int j = k >> 1; j > 0; j >>= 1) {
            __syncthreads();
            const int jm1 = j - 1;
#pragma unroll
            for (int q = 0; q < 4; q++) {
                int p_  = tid + 256 * q;
                int i   = ((p_ & ~jm1) << 1) | (p_ & jm1);
                int ix  = i + j;
                unsigned long long a = fb[i], bv = fb[ix];
                bool desc = ((i & k) == 0);
                if (desc ? (a < bv) : (a > bv)) { fb[i] = bv; fb[ix] = a; }
            }
        }
    }
    __syncthreads();
    if (tid < 32) {
        int kept = nms_scan(fb, NN, b, c, mb, tid);
        if (tid == 0) g_ccnt[b][c] = kept;
    }
}

// ---------------------------------------------------------------------------
// Kernel 3: per-batch top-200. grid(B), 512 threads.
//   3-level radix-select on hi-32 score bits (register counters at level 3,
//   warp-scan cutoffs) -> gather -> 512 bitonic -> emit.
// ---------------------------------------------------------------------------
__global__ __launch_bounds__(512) void topk_kernel(const float* __restrict__ x,
                                                   float* __restrict__ out) {
    const int b = blockIdx.x;
    const int tid = threadIdx.x;
    __shared__ int s_cnt[CC];
    __shared__ int s_hist[256];
    __shared__ unsigned long long s_key[512];
    __shared__ uint32_t s_pay[512];
    __shared__ int s_T, s_cut, s_rem, s_num;

    if (tid == 0) { s_T = 0; s_num = 0; }
    if (tid < 256) s_hist[tid] = 0;
    if (tid < CC) s_cnt[tid] = g_ccnt[b][tid];
    __syncthreads();

    // hi-32 words of g_ckey[b] (little-endian: hi at odd 4B offsets)
    const uint32_t* ck_hi = reinterpret_cast<const uint32_t*>(&g_ckey[b][0][0]) + 1;

    // ---- sweep 1: count T + level-3 histogram (hot bins 0x3C..0x3F) ----
    {
        int c0 = 0, c1 = 0, c2 = 0, c3 = 0, myT = 0;
        for (int idx = tid; idx < CC * OUT_K; idx += 512) {
            int c = idx / OUT_K, slot = idx - c * OUT_K;
            if (slot < s_cnt[c]) {
                uint32_t d = (__ldg(ck_hi + 2 * idx) >> 24) - 0x3Cu;
                myT++;
                c0 += (d == 0); c1 += (d == 1); c2 += (d == 2); c3 += (d == 3);
            }
        }
        if (myT) atomicAdd(&s_T, myT);
        if (c0) atomicAdd(&s_hist[0x3C], c0);
        if (c1) atomicAdd(&s_hist[0x3D], c1);
        if (c2) atomicAdd(&s_hist[0x3E], c2);
        if (c3) atomicAdd(&s_hist[0x3F], c3);
    }
    __syncthreads();
    const int T = s_T;
    const int kinit = (T < OUT_K) ? T : OUT_K;
    uint32_t S = 0;

    if (kinit > 0) {
        // level 3 cutoff
        warp_suffix_cut(s_hist, kinit, tid, &s_cut, &s_rem);
        __syncthreads();
        S = ((uint32_t)s_cut) << 24;
        int k = s_rem;
        if (tid < 256) s_hist[tid] = 0;
        __syncthreads();

        // level 2
        for (int idx = tid; idx < CC * OUT_K; idx += 512) {
            int c = idx / OUT_K, slot = idx - c * OUT_K;
            if (slot < s_cnt[c]) {
                uint32_t hi = __ldg(ck_hi + 2 * idx);
                if ((hi >> 24) == (S >> 24))
                    atomicAdd(&s_hist[(hi >> 16) & 255], 1);
            }
        }
        __syncthreads();
        warp_suffix_cut(s_hist, k, tid, &s_cut, &s_rem);
        __syncthreads();
        S |= ((uint32_t)s_cut) << 16;
        k = s_rem;
        if (tid < 256) s_hist[tid] = 0;
        __syncthreads();

        // level 1
        for (int idx = tid; idx < CC * OUT_K; idx += 512) {
            int c = idx / OUT_K, slot = idx - c * OUT_K;
            if (slot < s_cnt[c]) {
                uint32_t hi = __ldg(ck_hi + 2 * idx);
                if ((hi >> 16) == (S >> 16))
                    atomicAdd(&s_hist[(hi >> 8) & 255], 1);
            }
        }
        __syncthreads();
        warp_suffix_cut(s_hist, k, tid, &s_cut, &s_rem);
        __syncthreads();
        S |= ((uint32_t)s_cut) << 8;       // 24-bit prefix, low byte 0

        // gather: hi >= S (count <= ~(200 + prefix-bin size), capped 512)
        for (int idx = tid; idx < CC * OUT_K; idx += 512) {
            int c = idx / OUT_K, slot = idx - c * OUT_K;
            if (slot < s_cnt[c]) {
                uint32_t hi = __ldg(ck_hi + 2 * idx);
                if (hi >= S) {
                    int p_ = atomicAdd(&s_num, 1);
                    if (p_ < 512) {
                        s_key[p_] = g_ckey[b][0][idx];   // flat indexing over [CC][OUT_K]
                        s_pay[p_] = (uint32_t)idx;
                    }
                }
            }
        }
    }
    __syncthreads();
    const int num = s_num < 512 ? s_num : 512;
    for (int i2 = num + tid; i2 < 512; i2 += 512) { s_key[i2] = 0ull; s_pay[i2] = 0u; }
    __syncthreads();

    // bitonic sort 512 desc (256 active pairs; keys unique -> deterministic)
#pragma unroll 1
    for (int kk = 2; kk <= 512; kk <<= 1) {
#pragma unroll 1
        for (int j = kk >> 1; j > 0; j >>= 1) {
            if (tid < 256) {
                int i2 = ((tid & ~(j - 1)) << 1) | (tid & (j - 1));
                int ix = i2 + j;
                unsigned long long a = s_key[i2], bb2 = s_key[ix];
                bool desc2 = ((i2 & kk) == 0);
                if (desc2 ? (a < bb2) : (a > bb2)) {
                    s_key[i2] = bb2; s_key[ix] = a;
                    uint32_t tp = s_pay[i2]; s_pay[i2] = s_pay[ix]; s_pay[ix] = tp;
                }
            }
            __syncthreads();
        }
    }

    if (tid < OUT_K) {
        float* o = out + ((size_t)b * OUT_K + tid) * 6;
        if (tid < kinit) {
            unsigned long long key = s_key[tid];
            uint32_t pay = s_pay[tid];
            int c = pay / OUT_K, slot = pay - c * OUT_K;
            int bi = g_cbox[b][c][slot];
            const float* bx = x + ((size_t)b * NN + bi) * ROWF;
            o[0] = (float)c;
            o[1] = __uint_as_float((uint32_t)(key >> 32));
            o[2] = fminf(fmaxf(bx[0], 0.f), 1.f);
            o[3] = fminf(fmaxf(bx[1], 0.f), 1.f);
            o[4] = fminf(fmaxf(bx[2], 0.f), 1.f);
            o[5] = fminf(fmaxf(bx[3], 0.f), 1.f);
        } else {
            o[0] = o[1] = o[2] = o[3] = o[4] = o[5] = 0.f;
        }
    }
}

extern "C" void kernel_launch(void* const* d_in, const int* in_sizes, int n_in,
                              void* d_out, int out_size) {
    const float* x = (const float*)d_in[0];
    float* out = (float*)d_out;
    (void)in_sizes; (void)n_in; (void)out_size;

    dim3 g0(NN / 32, BB);
    transpose_kernel<<<g0, 256>>>(x);
    dim3 g1(NN / 16, BB);
    iou_mask_kernel<<<g1, 256>>>(x);
    dim3 g2(CC, BB);
    nms_kernel<<<g2, 256>>>();
    topk_kernel<<<BB, 512>>>(x, out);
}